// round 1
// baseline (speedup 1.0000x reference)
#include <cuda_runtime.h>
#include <math.h>

// Problem shapes (fixed by the dataset's setup_inputs):
//   B=64 samples, F=512 features, S=8192 signs, E=500000 edges, D=1024 diseases.
#define BB   64
#define FF   512
#define S_MAX 8192
#define E_MAX 500000
#define D_MAX 1024
#define EPSV 1e-8f
#define ETA  0.01f

// ---------------- device scratch (static: no allocations allowed) ------------
__device__ float g_HnT[FF * BB];        // normalized heatmap, transposed [f][b]
__device__ float g_gnorm[BB];           // ||grad_b||
__device__ float g_sinv[S_MAX];         // 1/(||S_s|| + eps)
__device__ float g_simT[S_MAX * BB];    // sim transposed: [s][b]
__device__ int   g_cnt[D_MAX];
__device__ int   g_cursor[D_MAX];
__device__ int   g_start[D_MAX + 1];
__device__ int2  g_epack[E_MAX];        // (sign, weight-bits) bucketed by disease

// ---------------- K1: normalize H rows (-> HnT) + grad norms ----------------
__global__ void prep_h_kernel(const float* __restrict__ H,
                              const float* __restrict__ G) {
    int b = blockIdx.x;            // 0..63
    int t = threadIdx.x;           // 128 threads, 4 floats each
    float4 hv = reinterpret_cast<const float4*>(H + b * FF)[t];
    float4 gv = reinterpret_cast<const float4*>(G + b * FF)[t];
    float sh = hv.x * hv.x + hv.y * hv.y + hv.z * hv.z + hv.w * hv.w;
    float sg = gv.x * gv.x + gv.y * gv.y + gv.z * gv.z + gv.w * gv.w;
    #pragma unroll
    for (int o = 16; o > 0; o >>= 1) {
        sh += __shfl_down_sync(0xffffffffu, sh, o);
        sg += __shfl_down_sync(0xffffffffu, sg, o);
    }
    __shared__ float wsh[4], wsg[4];
    __shared__ float s_inv;
    if ((t & 31) == 0) { wsh[t >> 5] = sh; wsg[t >> 5] = sg; }
    __syncthreads();
    if (t == 0) {
        float th = wsh[0] + wsh[1] + wsh[2] + wsh[3];
        float tg = wsg[0] + wsg[1] + wsg[2] + wsg[3];
        s_inv = 1.0f / (sqrtf(th) + EPSV);
        g_gnorm[b] = sqrtf(tg);
    }
    __syncthreads();
    float inv = s_inv;
    int f = 4 * t;
    g_HnT[(f + 0) * BB + b] = hv.x * inv;
    g_HnT[(f + 1) * BB + b] = hv.y * inv;
    g_HnT[(f + 2) * BB + b] = hv.z * inv;
    g_HnT[(f + 3) * BB + b] = hv.w * inv;
}

// ---------------- K2: per-sign inverse norms --------------------------------
__global__ void snorm_kernel(const float* __restrict__ SF) {
    int s = blockIdx.x;
    int t = threadIdx.x;           // 128 threads
    float4 v = reinterpret_cast<const float4*>(SF + (size_t)s * FF)[t];
    float ss = v.x * v.x + v.y * v.y + v.z * v.z + v.w * v.w;
    #pragma unroll
    for (int o = 16; o > 0; o >>= 1) ss += __shfl_down_sync(0xffffffffu, ss, o);
    __shared__ float ws[4];
    if ((t & 31) == 0) ws[t >> 5] = ss;
    __syncthreads();
    if (t == 0) g_sinv[s] = 1.0f / (sqrtf(ws[0] + ws[1] + ws[2] + ws[3]) + EPSV);
}

// ---------------- K3: zero bucket counters ----------------------------------
__global__ void zero_kernel(int D) {
    int t = threadIdx.x;
    if (t < D) { g_cnt[t] = 0; g_cursor[t] = 0; }
}

// ---------------- K4: histogram over diseases -------------------------------
__global__ void hist_kernel(const int* __restrict__ ed, int E) {
    int e = blockIdx.x * blockDim.x + threadIdx.x;
    if (e < E) atomicAdd(&g_cnt[ed[e]], 1);
}

// ---------------- K5: exclusive scan -> bucket starts (D <= 1024) -----------
__global__ void scan_kernel(int D) {
    __shared__ int sc[D_MAX];
    int t = threadIdx.x;           // 1024 threads
    sc[t] = (t < D) ? g_cnt[t] : 0;
    __syncthreads();
    #pragma unroll
    for (int off = 1; off < D_MAX; off <<= 1) {
        int v = sc[t];
        int a = (t >= off) ? sc[t - off] : 0;
        __syncthreads();
        sc[t] = v + a;
        __syncthreads();
    }
    if (t < D) g_start[t + 1] = sc[t];
    if (t == 0) g_start[0] = 0;
}

// ---------------- K6: scatter edges into buckets, pre-gathering (s, w) ------
__global__ void scat_kernel(const float* __restrict__ ew,
                            const int* __restrict__ ed,
                            const int* __restrict__ es, int E) {
    int e = blockIdx.x * blockDim.x + threadIdx.x;
    if (e >= E) return;
    int d = ed[e];
    int pos = atomicAdd(&g_cursor[d], 1);
    g_epack[g_start[d] + pos] = make_int2(es[e], __float_as_int(ew[e]));
}

// ---------------- K7: sim GEMM: simT[s][b] = (Hn_b . Sn_s + 1)/2 ------------
// Block: 256 threads, 32 s-rows. Smem: HnT[512][64] (128KB) + pre-scaled
// S-tile transposed with pad [512][33] (67KB). Micro-tile per thread: 4b x 2s.
#define SIM_SB   32
#define SIM_SMEM ((FF * BB + FF * 33) * (int)sizeof(float))
__global__ void sim_kernel(const float* __restrict__ SF) {
    extern __shared__ float sm[];
    float* sHnT   = sm;               // FF*BB floats
    float* sStage = sm + FF * BB;     // FF*33 floats, [f][sl]
    int t = threadIdx.x;              // 256
    int s0 = blockIdx.x * SIM_SB;

    for (int i = t; i < FF * BB; i += 256) sHnT[i] = g_HnT[i];
    for (int i = t; i < SIM_SB * FF; i += 256) {
        int sl = i >> 9;              // i / 512
        int f  = i & (FF - 1);
        sStage[f * 33 + sl] = SF[(size_t)(s0 + sl) * FF + f] * g_sinv[s0 + sl];
    }
    __syncthreads();

    int bq = t & 15;                  // b = 4*bq
    int sg = t >> 4;                  // sl = 2*sg, 2*sg+1
    float a00 = 0.f, a01 = 0.f, a02 = 0.f, a03 = 0.f;
    float a10 = 0.f, a11 = 0.f, a12 = 0.f, a13 = 0.f;
    const float* hp = sHnT + 4 * bq;
    const float* sp = sStage + 2 * sg;
    #pragma unroll 4
    for (int f = 0; f < FF; f++) {
        float4 hn = *reinterpret_cast<const float4*>(hp + f * 64);
        float sv0 = sp[f * 33 + 0];
        float sv1 = sp[f * 33 + 1];
        a00 += hn.x * sv0; a01 += hn.y * sv0; a02 += hn.z * sv0; a03 += hn.w * sv0;
        a10 += hn.x * sv1; a11 += hn.y * sv1; a12 += hn.z * sv1; a13 += hn.w * sv1;
    }
    int sa = s0 + 2 * sg;
    *reinterpret_cast<float4*>(&g_simT[sa * 64 + 4 * bq]) =
        make_float4((a00 + 1.f) * 0.5f, (a01 + 1.f) * 0.5f,
                    (a02 + 1.f) * 0.5f, (a03 + 1.f) * 0.5f);
    *reinterpret_cast<float4*>(&g_simT[(sa + 1) * 64 + 4 * bq]) =
        make_float4((a10 + 1.f) * 0.5f, (a11 + 1.f) * 0.5f,
                    (a12 + 1.f) * 0.5f, (a13 + 1.f) * 0.5f);
}

// ---------------- K8: per-disease gather-reduce -> out -----------------------
// One block per disease d. 128 threads = 4 edge-groups x 32 lanes.
// Lane l accumulates batch pair (2l, 2l+1) as float2.
__global__ void out_kernel(float* __restrict__ out, int D) {
    int d  = blockIdx.x;
    int t  = threadIdx.x;             // 128
    int l  = t & 31;
    int eg = t >> 5;                  // 0..3
    int i0 = g_start[d];
    int i1 = g_start[d + 1];
    float ax = 0.f, ay = 0.f;
    #pragma unroll 4
    for (int i = i0 + eg; i < i1; i += 4) {
        int2 p = g_epack[i];
        float w = __int_as_float(p.y);
        float2 sv = *reinterpret_cast<const float2*>(&g_simT[p.x * 64 + 2 * l]);
        ax += w * sv.x;
        ay += w * sv.y;
    }
    __shared__ float sx[128], sy[128];
    sx[t] = ax; sy[t] = ay;
    __syncthreads();
    if (eg == 0) {
        float tx = sx[l] + sx[32 + l] + sx[64 + l] + sx[96 + l];
        float ty = sy[l] + sy[32 + l] + sy[64 + l] + sy[96 + l];
        int b0 = 2 * l;
        out[(size_t)b0 * D + d]       = ETA * g_gnorm[b0]     * tx;
        out[(size_t)(b0 + 1) * D + d] = ETA * g_gnorm[b0 + 1] * ty;
    }
}

// ---------------- launch -----------------------------------------------------
extern "C" void kernel_launch(void* const* d_in, const int* in_sizes, int n_in,
                              void* d_out, int out_size) {
    const float* H  = (const float*)d_in[0];   // [B,F]
    const float* G  = (const float*)d_in[1];   // [B,F]
    const float* SF = (const float*)d_in[2];   // [S,F]
    const float* ew = (const float*)d_in[3];   // [E]
    const int*   ed = (const int*)d_in[4];     // [E]
    const int*   es = (const int*)d_in[5];     // [E]
    float* out = (float*)d_out;

    int Bv = in_sizes[0] / FF;                 // 64
    int S  = in_sizes[2] / FF;                 // 8192
    int E  = in_sizes[3];                      // 500000
    int D  = out_size / Bv;                    // 1024

    prep_h_kernel<<<Bv, 128>>>(H, G);
    snorm_kernel<<<S, 128>>>(SF);
    zero_kernel<<<1, 1024>>>(D);
    hist_kernel<<<(E + 255) / 256, 256>>>(ed, E);
    scan_kernel<<<1, 1024>>>(D);
    scat_kernel<<<(E + 255) / 256, 256>>>(ew, ed, es, E);

    static int smem_set = 0;
    if (!smem_set) {
        cudaFuncSetAttribute(sim_kernel,
                             cudaFuncAttributeMaxDynamicSharedMemorySize,
                             SIM_SMEM);
        smem_set = 1;
    }
    sim_kernel<<<S / SIM_SB, 256, SIM_SMEM>>>(SF);
    out_kernel<<<D, 128>>>(out, D);
}

// round 2
// speedup vs baseline: 1.5119x; 1.5119x over previous
#include <cuda_runtime.h>
#include <cuda_fp16.h>
#include <math.h>

// Shapes fixed by the dataset: B=64, F=512, S=8192, E=500000, D=1024.
#define BB    64
#define FF    512
#define S_MAX 8192
#define E_MAX 500000
#define D_MAX 1024
#define NBLK  256            // partition blocks for hist/scatter
#define EPSV  1e-8f
#define ETA   0.01f

// ---------------- device scratch (static: no allocations allowed) ------------
__device__ float  g_HnT[FF * BB];          // normalized heatmap, transposed [f][b]
__device__ float  g_gnorm[BB];             // ||grad_b||
__device__ __half g_simT[S_MAX * BB];      // sim transposed [s][b], fp16
__device__ int    g_blkcnt[NBLK * D_MAX];  // per-block histograms -> local prefixes
__device__ int    g_start[D_MAX + 1];      // bucket starts
__device__ int2   g_epack[E_MAX];          // (sign, weight-bits) bucketed by disease

// ---------------- K1: normalize H rows (-> HnT) + grad norms ----------------
__global__ void prep_h_kernel(const float* __restrict__ H,
                              const float* __restrict__ G) {
    int b = blockIdx.x;            // 0..63
    int t = threadIdx.x;           // 128 threads, 4 floats each
    float4 hv = reinterpret_cast<const float4*>(H + b * FF)[t];
    float4 gv = reinterpret_cast<const float4*>(G + b * FF)[t];
    float sh = hv.x * hv.x + hv.y * hv.y + hv.z * hv.z + hv.w * hv.w;
    float sg = gv.x * gv.x + gv.y * gv.y + gv.z * gv.z + gv.w * gv.w;
    #pragma unroll
    for (int o = 16; o > 0; o >>= 1) {
        sh += __shfl_down_sync(0xffffffffu, sh, o);
        sg += __shfl_down_sync(0xffffffffu, sg, o);
    }
    __shared__ float wsh[4], wsg[4];
    __shared__ float s_inv;
    if ((t & 31) == 0) { wsh[t >> 5] = sh; wsg[t >> 5] = sg; }
    __syncthreads();
    if (t == 0) {
        float th = wsh[0] + wsh[1] + wsh[2] + wsh[3];
        float tg = wsg[0] + wsg[1] + wsg[2] + wsg[3];
        s_inv = 1.0f / (sqrtf(th) + EPSV);
        g_gnorm[b] = sqrtf(tg);
    }
    __syncthreads();
    float inv = s_inv;
    int f = 4 * t;
    g_HnT[(f + 0) * BB + b] = hv.x * inv;
    g_HnT[(f + 1) * BB + b] = hv.y * inv;
    g_HnT[(f + 2) * BB + b] = hv.z * inv;
    g_HnT[(f + 3) * BB + b] = hv.w * inv;
}

// ---------------- K2: per-block privatized histogram ------------------------
__global__ void hist_kernel(const int* __restrict__ ed, int E, int CH) {
    __shared__ int h[D_MAX];
    int t = threadIdx.x;           // 256
    for (int i = t; i < D_MAX; i += 256) h[i] = 0;
    __syncthreads();
    int e0 = blockIdx.x * CH;
    int e1 = min(E, e0 + CH);
    for (int e = e0 + t; e < e1; e += 256) atomicAdd(&h[ed[e]], 1);
    __syncthreads();
    int* dst = g_blkcnt + blockIdx.x * D_MAX;
    for (int i = t; i < D_MAX; i += 256) dst[i] = h[i];
}

// ---------------- K3: scan (1 block): per-block local prefixes + g_start ----
__global__ void scan_kernel(int E) {
    __shared__ int sc[D_MAX];
    int t = threadIdx.x;           // 1024 = D
    int run = 0;
    #pragma unroll 8
    for (int blk = 0; blk < NBLK; blk++) {
        int idx = blk * D_MAX + t;
        int c = g_blkcnt[idx];
        g_blkcnt[idx] = run;       // within-disease exclusive prefix over blocks
        run += c;
    }
    sc[t] = run;                   // total count for disease t
    __syncthreads();
    #pragma unroll
    for (int off = 1; off < D_MAX; off <<= 1) {
        int v = sc[t];
        int a = (t >= off) ? sc[t - off] : 0;
        __syncthreads();
        sc[t] = v + a;             // inclusive scan
        __syncthreads();
    }
    g_start[t + 1] = sc[t];
    if (t == 0) g_start[0] = 0;
}

// ---------------- K4: deterministic-offset scatter (smem cursors) -----------
__global__ void scat_kernel(const float* __restrict__ ew,
                            const int* __restrict__ ed,
                            const int* __restrict__ es, int E, int CH) {
    __shared__ int cur[D_MAX];
    int t = threadIdx.x;           // 256
    const int* off = g_blkcnt + blockIdx.x * D_MAX;
    for (int i = t; i < D_MAX; i += 256) cur[i] = off[i] + g_start[i];
    __syncthreads();
    int e0 = blockIdx.x * CH;
    int e1 = min(E, e0 + CH);
    for (int e = e0 + t; e < e1; e += 256) {
        int d = ed[e];
        int pos = atomicAdd(&cur[d], 1);
        g_epack[pos] = make_int2(es[e], __float_as_int(ew[e]));
    }
}

// ---------------- K5: sim GEMM with fused sign-norm --------------------------
// Block: 256 threads, 32 s-rows. Smem: HnT[512][64] (128KB) + S-tile
// transposed w/ pad [512][33] (67.5KB). Micro-tile per thread: 4b x 2s.
#define SIM_SB   32
#define SIM_SMEM ((FF * BB + FF * 33) * (int)sizeof(float))
__global__ void sim_kernel(const float* __restrict__ SF) {
    extern __shared__ float sm[];
    float* sHnT   = sm;               // FF*BB floats
    float* sStage = sm + FF * BB;     // FF*33 floats, [f][sl]
    __shared__ float red[8][32];
    __shared__ float s_sinv[32];
    int t = threadIdx.x;              // 256
    int s0 = blockIdx.x * SIM_SB;

    for (int i = t; i < FF * BB; i += 256) sHnT[i] = g_HnT[i];
    for (int i = t; i < SIM_SB * FF; i += 256) {
        int sl = i >> 9;              // i / 512
        int f  = i & (FF - 1);
        sStage[f * 33 + sl] = SF[(size_t)(s0 + sl) * FF + f];
    }
    __syncthreads();

    // fused per-row norm of the staged S tile
    {
        int sl = t & 31;
        int c  = t >> 5;              // 8 chunks of 64 features
        float ss = 0.f;
        #pragma unroll 8
        for (int j = 0; j < 64; j++) {
            float v = sStage[(c * 64 + j) * 33 + sl];
            ss += v * v;
        }
        red[c][sl] = ss;
        __syncthreads();
        if (t < 32) {
            float tot = 0.f;
            #pragma unroll
            for (int c2 = 0; c2 < 8; c2++) tot += red[c2][t];
            s_sinv[t] = 1.0f / (sqrtf(tot) + EPSV);
        }
        __syncthreads();
        for (int i = t; i < SIM_SB * FF; i += 256) {
            int sl2 = i >> 9;
            int f   = i & (FF - 1);
            sStage[f * 33 + sl2] *= s_sinv[sl2];
        }
        __syncthreads();
    }

    int bq = t & 15;                  // b = 4*bq
    int sg = t >> 4;                  // sl = 2*sg, 2*sg+1
    float a00 = 0.f, a01 = 0.f, a02 = 0.f, a03 = 0.f;
    float a10 = 0.f, a11 = 0.f, a12 = 0.f, a13 = 0.f;
    const float* hp = sHnT + 4 * bq;
    const float* sp = sStage + 2 * sg;
    #pragma unroll 4
    for (int f = 0; f < FF; f++) {
        float4 hn = *reinterpret_cast<const float4*>(hp + f * 64);
        float sv0 = sp[f * 33 + 0];
        float sv1 = sp[f * 33 + 1];
        a00 += hn.x * sv0; a01 += hn.y * sv0; a02 += hn.z * sv0; a03 += hn.w * sv0;
        a10 += hn.x * sv1; a11 += hn.y * sv1; a12 += hn.z * sv1; a13 += hn.w * sv1;
    }
    int sa = s0 + 2 * sg;
    __half2* o0 = reinterpret_cast<__half2*>(&g_simT[sa * 64 + 4 * bq]);
    o0[0] = __floats2half2_rn((a00 + 1.f) * 0.5f, (a01 + 1.f) * 0.5f);
    o0[1] = __floats2half2_rn((a02 + 1.f) * 0.5f, (a03 + 1.f) * 0.5f);
    __half2* o1 = reinterpret_cast<__half2*>(&g_simT[(sa + 1) * 64 + 4 * bq]);
    o1[0] = __floats2half2_rn((a10 + 1.f) * 0.5f, (a11 + 1.f) * 0.5f);
    o1[1] = __floats2half2_rn((a12 + 1.f) * 0.5f, (a13 + 1.f) * 0.5f);
}

// ---------------- K6: per-disease gather-reduce -> out -----------------------
// One block per disease d. 256 threads = 8 edge-groups x 32 lanes.
// Lane l accumulates batch pair (2l, 2l+1); per edge: one 128B simT line.
__global__ void out_kernel(float* __restrict__ out, int D) {
    int d  = blockIdx.x;
    int t  = threadIdx.x;             // 256
    int l  = t & 31;
    int eg = t >> 5;                  // 0..7
    int i0 = g_start[d];
    int i1 = g_start[d + 1];
    float ax = 0.f, ay = 0.f;
    #pragma unroll 2
    for (int i = i0 + eg; i < i1; i += 8) {
        int2 p = g_epack[i];
        float w = __int_as_float(p.y);
        __half2 sv = *reinterpret_cast<const __half2*>(&g_simT[p.x * 64 + 2 * l]);
        float2 f = __half22float2(sv);
        ax += w * f.x;
        ay += w * f.y;
    }
    __shared__ float sx[256], sy[256];
    sx[t] = ax; sy[t] = ay;
    __syncthreads();
    if (eg == 0) {
        float tx = 0.f, ty = 0.f;
        #pragma unroll
        for (int k = 0; k < 8; k++) { tx += sx[32 * k + l]; ty += sy[32 * k + l]; }
        int b0 = 2 * l;
        out[(size_t)b0 * D + d]       = ETA * g_gnorm[b0]     * tx;
        out[(size_t)(b0 + 1) * D + d] = ETA * g_gnorm[b0 + 1] * ty;
    }
}

// ---------------- launch -----------------------------------------------------
extern "C" void kernel_launch(void* const* d_in, const int* in_sizes, int n_in,
                              void* d_out, int out_size) {
    const float* H  = (const float*)d_in[0];   // [B,F]
    const float* G  = (const float*)d_in[1];   // [B,F]
    const float* SF = (const float*)d_in[2];   // [S,F]
    const float* ew = (const float*)d_in[3];   // [E]
    const int*   ed = (const int*)d_in[4];     // [E]
    const int*   es = (const int*)d_in[5];     // [E]
    float* out = (float*)d_out;

    int Bv = in_sizes[0] / FF;                 // 64
    int S  = in_sizes[2] / FF;                 // 8192
    int E  = in_sizes[3];                      // 500000
    int D  = out_size / Bv;                    // 1024
    int CH = (E + NBLK - 1) / NBLK;            // edges per partition block

    static int smem_set = 0;
    if (!smem_set) {
        cudaFuncSetAttribute(sim_kernel,
                             cudaFuncAttributeMaxDynamicSharedMemorySize,
                             SIM_SMEM);
        smem_set = 1;
    }

    prep_h_kernel<<<Bv, 128>>>(H, G);
    hist_kernel<<<NBLK, 256>>>(ed, E, CH);
    scan_kernel<<<1, 1024>>>(E);
    scat_kernel<<<NBLK, 256>>>(ew, ed, es, E, CH);
    sim_kernel<<<S / SIM_SB, 256, SIM_SMEM>>>(SF);
    out_kernel<<<D, 256>>>(out, D);
}

// round 3
// speedup vs baseline: 1.9360x; 1.2805x over previous
#include <cuda_runtime.h>
#include <cuda_fp16.h>
#include <math.h>

// Shapes fixed by the dataset: B=64, F=512, S=8192, E=500000, D=1024.
#define BB    64
#define FF    512
#define S_MAX 8192
#define E_MAX 500000
#define D_MAX 1024
#define NBLK  148            // partition blocks for hist/scatter (1 wave)
#define EPSV  1e-8f
#define ETA   0.01f

// ---------------- device scratch (static: no allocations allowed) ------------
__device__ float  g_HnT[FF * BB];          // normalized heatmap, transposed [f][b]
__device__ float  g_gnorm[BB];             // ||grad_b||
__device__ __half g_simT[S_MAX * BB];      // sim transposed [s][b], fp16
__device__ int    g_blkcnt[NBLK * D_MAX];  // per-block histograms -> local prefixes
__device__ int    g_start[D_MAX + 1];      // bucket starts
__device__ int2   g_epack[E_MAX];          // (sign, weight-bits) bucketed by disease

// ---------------- K1: normalize H rows (-> HnT) + grad norms ----------------
__global__ void prep_h_kernel(const float* __restrict__ H,
                              const float* __restrict__ G) {
    int b = blockIdx.x;            // 0..63
    int t = threadIdx.x;           // 128 threads, 4 floats each
    float4 hv = reinterpret_cast<const float4*>(H + b * FF)[t];
    float4 gv = reinterpret_cast<const float4*>(G + b * FF)[t];
    float sh = hv.x * hv.x + hv.y * hv.y + hv.z * hv.z + hv.w * hv.w;
    float sg = gv.x * gv.x + gv.y * gv.y + gv.z * gv.z + gv.w * gv.w;
    #pragma unroll
    for (int o = 16; o > 0; o >>= 1) {
        sh += __shfl_down_sync(0xffffffffu, sh, o);
        sg += __shfl_down_sync(0xffffffffu, sg, o);
    }
    __shared__ float wsh[4], wsg[4];
    __shared__ float s_inv;
    if ((t & 31) == 0) { wsh[t >> 5] = sh; wsg[t >> 5] = sg; }
    __syncthreads();
    if (t == 0) {
        float th = wsh[0] + wsh[1] + wsh[2] + wsh[3];
        float tg = wsg[0] + wsg[1] + wsg[2] + wsg[3];
        s_inv = 1.0f / (sqrtf(th) + EPSV);
        g_gnorm[b] = sqrtf(tg);
    }
    __syncthreads();
    float inv = s_inv;
    int f = 4 * t;
    g_HnT[(f + 0) * BB + b] = hv.x * inv;
    g_HnT[(f + 1) * BB + b] = hv.y * inv;
    g_HnT[(f + 2) * BB + b] = hv.z * inv;
    g_HnT[(f + 3) * BB + b] = hv.w * inv;
}

// ---------------- K2: per-block privatized histogram ------------------------
__global__ void hist_kernel(const int* __restrict__ ed, int E, int CH) {
    __shared__ int h[D_MAX];
    int t = threadIdx.x;           // 512
    h[t] = 0; h[t + 512] = 0;
    __syncthreads();
    int e0 = blockIdx.x * CH;
    int e1 = min(E, e0 + CH);
    for (int e = e0 + t; e < e1; e += 512) atomicAdd(&h[ed[e]], 1);
    __syncthreads();
    int* dst = g_blkcnt + blockIdx.x * D_MAX;
    dst[t] = h[t]; dst[t + 512] = h[t + 512];
}

// ---------------- K3: scan (1 block): per-block local prefixes + g_start ----
__global__ void scan_kernel(int E) {
    __shared__ int sc[D_MAX];
    int t = threadIdx.x;           // 1024 = D
    int run = 0;
    #pragma unroll 4
    for (int blk = 0; blk < NBLK; blk++) {
        int idx = blk * D_MAX + t;
        int c = g_blkcnt[idx];
        g_blkcnt[idx] = run;       // within-disease exclusive prefix over blocks
        run += c;
    }
    sc[t] = run;                   // total count for disease t
    __syncthreads();
    #pragma unroll
    for (int off = 1; off < D_MAX; off <<= 1) {
        int v = sc[t];
        int a = (t >= off) ? sc[t - off] : 0;
        __syncthreads();
        sc[t] = v + a;             // inclusive scan
        __syncthreads();
    }
    g_start[t + 1] = sc[t];
    if (t == 0) g_start[0] = 0;
}

// ---------------- K4: deterministic-offset scatter (smem cursors) -----------
__global__ void scat_kernel(const float* __restrict__ ew,
                            const int* __restrict__ ed,
                            const int* __restrict__ es, int E, int CH) {
    __shared__ int cur[D_MAX];
    int t = threadIdx.x;           // 512
    const int* off = g_blkcnt + blockIdx.x * D_MAX;
    cur[t]       = off[t]       + g_start[t];
    cur[t + 512] = off[t + 512] + g_start[t + 512];
    __syncthreads();
    int e0 = blockIdx.x * CH;
    int e1 = min(E, e0 + CH);
    for (int e = e0 + t; e < e1; e += 512) {
        int d = ed[e];
        int pos = atomicAdd(&cur[d], 1);
        g_epack[pos] = make_int2(es[e], __float_as_int(ew[e]));
    }
}

// ---------------- K5: sim GEMM, 2 s-tiles per block, epilogue-applied sinv ---
// Block: 256 threads. Smem: HnT[512][64] (128KB, staged once) + S-tile
// transposed w/ pad [512][33] (67.5KB, restaged per tile).
// Micro-tile per thread: 4b x 2s. Epilogue: sim = dot*(0.5*sinv) + 0.5.
#define SIM_SB   32
#define SIM_SMEM ((FF * BB + FF * 33) * (int)sizeof(float))
__global__ void sim_kernel(const float* __restrict__ SF) {
    extern __shared__ float sm[];
    float* sHnT   = sm;               // FF*BB floats
    float* sStage = sm + FF * BB;     // FF*33 floats, [f][sl]
    __shared__ float red[8][33];
    __shared__ float s_scale[32];
    int t = threadIdx.x;              // 256

    // stage HnT once (vectorized)
    {
        const float4* src = reinterpret_cast<const float4*>(g_HnT);
        float4* dst = reinterpret_cast<float4*>(sHnT);
        #pragma unroll
        for (int i = 0; i < (FF * BB / 4) / 256; i++)   // 32 iters
            dst[t + i * 256] = src[t + i * 256];
    }

    #pragma unroll 1
    for (int tile = 0; tile < 2; tile++) {
        int s0 = (blockIdx.x * 2 + tile) * SIM_SB;
        __syncthreads();              // previous tile fully consumed
        // stage raw S tile transposed (vectorized reads)
        for (int i = t; i < SIM_SB * FF / 4; i += 256) {  // 16 iters
            int sl = i >> 7;          // 128 float4 per row
            int fq = i & 127;
            float4 v = reinterpret_cast<const float4*>(SF)[(size_t)(s0 + sl) * 128 + fq];
            int f = 4 * fq;
            sStage[(f + 0) * 33 + sl] = v.x;
            sStage[(f + 1) * 33 + sl] = v.y;
            sStage[(f + 2) * 33 + sl] = v.z;
            sStage[(f + 3) * 33 + sl] = v.w;
        }
        __syncthreads();
        // per-row squared sums
        {
            int sl = t & 31, c = t >> 5;
            float ss = 0.f;
            #pragma unroll 8
            for (int j = 0; j < 64; j++) {
                float v = sStage[(c * 64 + j) * 33 + sl];
                ss += v * v;
            }
            red[c][sl] = ss;
        }
        __syncthreads();
        if (t < 32) {
            float tot = 0.f;
            #pragma unroll
            for (int c = 0; c < 8; c++) tot += red[c][t];
            s_scale[t] = 0.5f / (sqrtf(tot) + EPSV);
        }
        __syncthreads();

        // main FFMA loop on raw S (scale applied in epilogue)
        int bq = t & 15;              // b = 4*bq
        int sg = t >> 4;              // sl = 2*sg, 2*sg+1
        float a00 = 0.f, a01 = 0.f, a02 = 0.f, a03 = 0.f;
        float a10 = 0.f, a11 = 0.f, a12 = 0.f, a13 = 0.f;
        const float* hp = sHnT + 4 * bq;
        const float* sp = sStage + 2 * sg;
        #pragma unroll 8
        for (int f = 0; f < FF; f++) {
            float4 hn = *reinterpret_cast<const float4*>(hp + f * 64);
            float sv0 = sp[f * 33 + 0];
            float sv1 = sp[f * 33 + 1];
            a00 += hn.x * sv0; a01 += hn.y * sv0; a02 += hn.z * sv0; a03 += hn.w * sv0;
            a10 += hn.x * sv1; a11 += hn.y * sv1; a12 += hn.z * sv1; a13 += hn.w * sv1;
        }
        float sc0 = s_scale[2 * sg];
        float sc1 = s_scale[2 * sg + 1];
        int sa = s0 + 2 * sg;
        __half2* o0 = reinterpret_cast<__half2*>(&g_simT[sa * 64 + 4 * bq]);
        o0[0] = __floats2half2_rn(a00 * sc0 + 0.5f, a01 * sc0 + 0.5f);
        o0[1] = __floats2half2_rn(a02 * sc0 + 0.5f, a03 * sc0 + 0.5f);
        __half2* o1 = reinterpret_cast<__half2*>(&g_simT[(sa + 1) * 64 + 4 * bq]);
        o1[0] = __floats2half2_rn(a10 * sc1 + 0.5f, a11 * sc1 + 0.5f);
        o1[1] = __floats2half2_rn(a12 * sc1 + 0.5f, a13 * sc1 + 0.5f);
    }
}

// ---------------- K6: per-disease gather-reduce -> out -----------------------
// One block per disease d. 256 threads = 8 edge-groups x 32 lanes.
// Lane l accumulates batch pair (2l, 2l+1); per edge: one 128B simT line.
__global__ void out_kernel(float* __restrict__ out, int D) {
    int d  = blockIdx.x;
    int t  = threadIdx.x;             // 256
    int l  = t & 31;
    int eg = t >> 5;                  // 0..7
    int i0 = g_start[d];
    int i1 = g_start[d + 1];
    float ax = 0.f, ay = 0.f;
    #pragma unroll 2
    for (int i = i0 + eg; i < i1; i += 8) {
        int2 p = g_epack[i];
        float w = __int_as_float(p.y);
        __half2 sv = *reinterpret_cast<const __half2*>(&g_simT[p.x * 64 + 2 * l]);
        float2 f = __half22float2(sv);
        ax += w * f.x;
        ay += w * f.y;
    }
    __shared__ float sx[256], sy[256];
    sx[t] = ax; sy[t] = ay;
    __syncthreads();
    if (eg == 0) {
        float tx = 0.f, ty = 0.f;
        #pragma unroll
        for (int k = 0; k < 8; k++) { tx += sx[32 * k + l]; ty += sy[32 * k + l]; }
        int b0 = 2 * l;
        out[(size_t)b0 * D + d]       = ETA * g_gnorm[b0]     * tx;
        out[(size_t)(b0 + 1) * D + d] = ETA * g_gnorm[b0 + 1] * ty;
    }
}

// ---------------- launch -----------------------------------------------------
extern "C" void kernel_launch(void* const* d_in, const int* in_sizes, int n_in,
                              void* d_out, int out_size) {
    const float* H  = (const float*)d_in[0];   // [B,F]
    const float* G  = (const float*)d_in[1];   // [B,F]
    const float* SF = (const float*)d_in[2];   // [S,F]
    const float* ew = (const float*)d_in[3];   // [E]
    const int*   ed = (const int*)d_in[4];     // [E]
    const int*   es = (const int*)d_in[5];     // [E]
    float* out = (float*)d_out;

    int Bv = in_sizes[0] / FF;                 // 64
    int S  = in_sizes[2] / FF;                 // 8192
    int E  = in_sizes[3];                      // 500000
    int D  = out_size / Bv;                    // 1024
    int CH = (E + NBLK - 1) / NBLK;            // edges per partition block

    static int smem_set = 0;
    if (!smem_set) {
        cudaFuncSetAttribute(sim_kernel,
                             cudaFuncAttributeMaxDynamicSharedMemorySize,
                             SIM_SMEM);
        smem_set = 1;
    }

    prep_h_kernel<<<Bv, 128>>>(H, G);
    hist_kernel<<<NBLK, 512>>>(ed, E, CH);
    scan_kernel<<<1, 1024>>>(E);
    scat_kernel<<<NBLK, 512>>>(ew, ed, es, E, CH);
    sim_kernel<<<S / (2 * SIM_SB), 256, SIM_SMEM>>>(SF);
    out_kernel<<<D, 256>>>(out, D);
}

// round 5
// speedup vs baseline: 2.9750x; 1.5366x over previous
#include <cuda_runtime.h>
#include <cuda_fp16.h>
#include <cuda_bf16.h>
#include <math.h>
#include <stdint.h>

// Shapes fixed by the dataset: B=64, F=512, S=8192, E=500000, D=1024.
#define BB    64
#define FF    512
#define S_MAX 8192
#define E_MAX 500000
#define D_MAX 1024
#define NBLK  148            // partition blocks for hist/scatter (1 wave)
#define EPSV  1e-8f
#define ETA   0.01f

// ---------------- device scratch (static: no allocations allowed) ------------
__device__ __nv_bfloat16 g_HnB[BB * FF];   // normalized heatmap, bf16 [b][f]
__device__ float  g_gnorm[BB];             // ||grad_b||
__device__ __half g_simT[S_MAX * BB];      // sim transposed [s][b], fp16
__device__ int    g_blkcnt[NBLK * D_MAX];  // per-block histograms -> local prefixes
__device__ int    g_cnt[D_MAX];            // per-disease totals
__device__ int    g_start[D_MAX + 1];      // bucket starts
__device__ int2   g_epack[E_MAX];          // (sign, weight-bits) bucketed by disease

// ================= portable tensor-core helpers (sm_80+) =====================
__device__ __forceinline__ uint32_t smem_u32(const void* p) {
    uint32_t a;
    asm("{ .reg .u64 t; cvta.to.shared.u64 t, %1; cvt.u32.u64 %0, t; }"
        : "=r"(a) : "l"(p));
    return a;
}
#define LDSM_X4(r, addr)                                                       \
    asm volatile("ldmatrix.sync.aligned.m8n8.x4.shared.b16 {%0,%1,%2,%3}, [%4];" \
        : "=r"((r)[0]), "=r"((r)[1]), "=r"((r)[2]), "=r"((r)[3])               \
        : "r"(addr))
__device__ __forceinline__ void mma_bf16(float* c, const uint32_t* a,
                                         uint32_t b0, uint32_t b1) {
    asm volatile(
        "mma.sync.aligned.m16n8k16.row.col.f32.bf16.bf16.f32 "
        "{%0,%1,%2,%3}, {%4,%5,%6,%7}, {%8,%9}, {%0,%1,%2,%3};"
        : "+f"(c[0]), "+f"(c[1]), "+f"(c[2]), "+f"(c[3])
        : "r"(a[0]), "r"(a[1]), "r"(a[2]), "r"(a[3]), "r"(b0), "r"(b1));
}

// ---------------- K1: normalize H rows (-> bf16) + grad norms ----------------
__global__ void prep_h_kernel(const float* __restrict__ H,
                              const float* __restrict__ G) {
    int b = blockIdx.x;            // 0..63
    int t = threadIdx.x;           // 128 threads, 4 floats each
    float4 hv = reinterpret_cast<const float4*>(H + b * FF)[t];
    float4 gv = reinterpret_cast<const float4*>(G + b * FF)[t];
    float sh = hv.x * hv.x + hv.y * hv.y + hv.z * hv.z + hv.w * hv.w;
    float sg = gv.x * gv.x + gv.y * gv.y + gv.z * gv.z + gv.w * gv.w;
    #pragma unroll
    for (int o = 16; o > 0; o >>= 1) {
        sh += __shfl_down_sync(0xffffffffu, sh, o);
        sg += __shfl_down_sync(0xffffffffu, sg, o);
    }
    __shared__ float wsh[4], wsg[4];
    __shared__ float s_inv;
    if ((t & 31) == 0) { wsh[t >> 5] = sh; wsg[t >> 5] = sg; }
    __syncthreads();
    if (t == 0) {
        float th = wsh[0] + wsh[1] + wsh[2] + wsh[3];
        float tg = wsg[0] + wsg[1] + wsg[2] + wsg[3];
        s_inv = 1.0f / (sqrtf(th) + EPSV);
        g_gnorm[b] = sqrtf(tg);
    }
    __syncthreads();
    float inv = s_inv;
    __nv_bfloat162 p0 = __floats2bfloat162_rn(hv.x * inv, hv.y * inv);
    __nv_bfloat162 p1 = __floats2bfloat162_rn(hv.z * inv, hv.w * inv);
    uint2 u;
    u.x = *reinterpret_cast<uint32_t*>(&p0);
    u.y = *reinterpret_cast<uint32_t*>(&p1);
    reinterpret_cast<uint2*>(g_HnB)[b * 128 + t] = u;
}

// ---------------- K2: per-block privatized histogram ------------------------
__global__ void hist_kernel(const int* __restrict__ ed, int E, int CH) {
    __shared__ int h[D_MAX];
    int t = threadIdx.x;           // 1024
    h[t] = 0;
    __syncthreads();
    int e0 = blockIdx.x * CH;
    int e1 = min(E, e0 + CH);
    for (int e = e0 + t; e < e1; e += 1024) atomicAdd(&h[ed[e]], 1);
    __syncthreads();
    g_blkcnt[blockIdx.x * D_MAX + t] = h[t];
}

// ---------------- K3a: parallel per-block prefix + disease totals -----------
__global__ void scan_pre_kernel() {
    int g  = blockIdx.x;           // 8 blocks, 128 diseases each
    int dl = threadIdx.x & 127;
    int c  = threadIdx.x >> 7;     // 8 chunks over NBLK
    int d  = g * 128 + dl;
    const int per = (NBLK + 7) / 8;
    int b0 = c * per, b1 = min(NBLK, b0 + per);
    int sum = 0;
    for (int blk = b0; blk < b1; blk++) sum += g_blkcnt[blk * D_MAX + d];
    __shared__ int ch[8][128];
    ch[c][dl] = sum;
    __syncthreads();
    if (c == 0) {
        int r = 0;
        #pragma unroll
        for (int j = 0; j < 8; j++) { int v = ch[j][dl]; ch[j][dl] = r; r += v; }
        g_cnt[d] = r;
    }
    __syncthreads();
    int run = ch[c][dl];
    for (int blk = b0; blk < b1; blk++) {
        int idx = blk * D_MAX + d;
        int v = g_blkcnt[idx];
        g_blkcnt[idx] = run;       // within-disease exclusive prefix over blocks
        run += v;
    }
}

// ---------------- K3b: scan disease totals -> g_start ------------------------
__global__ void scan_kernel() {
    __shared__ int sc[D_MAX];
    int t = threadIdx.x;           // 1024
    sc[t] = g_cnt[t];
    __syncthreads();
    #pragma unroll
    for (int off = 1; off < D_MAX; off <<= 1) {
        int v = sc[t];
        int a = (t >= off) ? sc[t - off] : 0;
        __syncthreads();
        sc[t] = v + a;
        __syncthreads();
    }
    g_start[t + 1] = sc[t];
    if (t == 0) g_start[0] = 0;
}

// ---------------- K4: deterministic-offset scatter (smem cursors) -----------
__global__ void scat_kernel(const float* __restrict__ ew,
                            const int* __restrict__ ed,
                            const int* __restrict__ es, int E, int CH) {
    __shared__ int cur[D_MAX];
    int t = threadIdx.x;           // 1024
    cur[t] = g_blkcnt[blockIdx.x * D_MAX + t] + g_start[t];
    __syncthreads();
    int e0 = blockIdx.x * CH;
    int e1 = min(E, e0 + CH);
    for (int e = e0 + t; e < e1; e += 1024) {
        int d = ed[e];
        int pos = atomicAdd(&cur[d], 1);
        g_epack[pos] = make_int2(es[e], __float_as_int(ew[e]));
    }
}

// ---------------- K5: sim via HMMA (mma.sync bf16) ---------------------------
// Per block: M=64 signs x N=64 batch x K=512. A = raw S tile bf16, B = Hn bf16,
// both at 1040-byte row pitch (conflict-free ldmatrix). 8 warps, each 16m x 32n.
// Epilogue: sim = dot*(0.5*sinv_s) + 0.5 -> fp16 g_simT.
#define APITCH   1040                       // bytes per 512-bf16 row (+16 pad)
#define SIM_A_OFF 0
#define SIM_B_OFF (64 * APITCH)
#define SIM_SMEM  (128 * APITCH)            // 133120 B

__global__ void __launch_bounds__(256, 1) sim_kernel(const float* __restrict__ SF) {
    extern __shared__ char sm[];
    __shared__ float s_sumsq[64];
    __shared__ float s_sinv[64];
    uint32_t smA = smem_u32(sm) + SIM_A_OFF;
    uint32_t smB = smem_u32(sm) + SIM_B_OFF;
    int t   = threadIdx.x;         // 256
    int wid = t >> 5;
    int lid = t & 31;
    int s0  = blockIdx.x * 64;

    if (t < 64) s_sumsq[t] = 0.0f;
    __syncthreads();

    // Stage A: S tile [64 rows][512 f] fp32 -> bf16, pitch 1040. Fused norms.
    #pragma unroll 4
    for (int i = t; i < 64 * 128; i += 256) {
        int row = i >> 7;
        int q   = i & 127;
        float4 v = reinterpret_cast<const float4*>(SF)[(size_t)(s0 + row) * 128 + q];
        float sq = v.x * v.x + v.y * v.y + v.z * v.z + v.w * v.w;
        #pragma unroll
        for (int o = 16; o > 0; o >>= 1) sq += __shfl_down_sync(0xffffffffu, sq, o);
        if (lid == 0) atomicAdd(&s_sumsq[row], sq);
        __nv_bfloat162 b0 = __floats2bfloat162_rn(v.x, v.y);
        __nv_bfloat162 b1 = __floats2bfloat162_rn(v.z, v.w);
        uint2 u;
        u.x = *reinterpret_cast<uint32_t*>(&b0);
        u.y = *reinterpret_cast<uint32_t*>(&b1);
        *reinterpret_cast<uint2*>(sm + SIM_A_OFF + row * APITCH + q * 8) = u;
    }
    // Stage B: Hn [64 rows][512 f] bf16 -> pitch 1040.
    #pragma unroll 4
    for (int i = t; i < 64 * 64; i += 256) {   // 16B chunks
        int row = i >> 6;
        int c16 = i & 63;
        uint4 u = reinterpret_cast<const uint4*>(g_HnB)[row * 64 + c16];
        *reinterpret_cast<uint4*>(sm + SIM_B_OFF + row * APITCH + c16 * 16) = u;
    }
    __syncthreads();
    if (t < 64) s_sinv[t] = 0.5f / (sqrtf(s_sumsq[t]) + EPSV);

    // Warp tile: m0 = 16*(wid>>1), n0 = 32*(wid&1). 4 n8-tiles per warp.
    int m0 = (wid >> 1) * 16;
    int n0 = (wid & 1) * 32;
    float c[16];
    #pragma unroll
    for (int j = 0; j < 16; j++) c[j] = 0.0f;

    // ldmatrix lane addresses (constant across k except k offset)
    uint32_t aBase = smA + (uint32_t)(m0 + (lid & 15)) * APITCH + ((lid >> 4) << 4);
    int brow = ((lid >> 4) << 3) + (lid & 7);
    uint32_t kofs = (((lid >> 3) & 1) << 4);
    uint32_t bBase0 = smB + (uint32_t)(n0 + brow) * APITCH + kofs;
    uint32_t bBase1 = smB + (uint32_t)(n0 + 16 + brow) * APITCH + kofs;
    __syncthreads();

    #pragma unroll 4
    for (int k = 0; k < FF; k += 16) {
        uint32_t a[4], b[8];
        LDSM_X4(a, aBase + k * 2);
        LDSM_X4(b, bBase0 + k * 2);
        LDSM_X4(b + 4, bBase1 + k * 2);
        mma_bf16(c + 0,  a, b[0], b[1]);
        mma_bf16(c + 4,  a, b[2], b[3]);
        mma_bf16(c + 8,  a, b[4], b[5]);
        mma_bf16(c + 12, a, b[6], b[7]);
    }

    // Epilogue: thread holds rows r0=m0+lid/4, r1=r0+8; cols 2*(lid&3)+... per tile.
    int r0 = m0 + (lid >> 2);
    int r1 = r0 + 8;
    int cb = 2 * (lid & 3);
    float sc0 = s_sinv[r0];
    float sc1 = s_sinv[r1];
    #pragma unroll
    for (int nt = 0; nt < 4; nt++) {
        int col = n0 + nt * 8 + cb;
        __half2 h0 = __floats2half2_rn(c[nt * 4 + 0] * sc0 + 0.5f,
                                       c[nt * 4 + 1] * sc0 + 0.5f);
        __half2 h1 = __floats2half2_rn(c[nt * 4 + 2] * sc1 + 0.5f,
                                       c[nt * 4 + 3] * sc1 + 0.5f);
        *reinterpret_cast<__half2*>(&g_simT[(size_t)(s0 + r0) * 64 + col]) = h0;
        *reinterpret_cast<__half2*>(&g_simT[(size_t)(s0 + r1) * 64 + col]) = h1;
    }
}

// ---------------- K6: per-disease gather-reduce -> out -----------------------
__global__ void out_kernel(float* __restrict__ out, int D) {
    int d  = blockIdx.x;
    int t  = threadIdx.x;             // 256
    int l  = t & 31;
    int eg = t >> 5;                  // 0..7
    int i0 = g_start[d];
    int i1 = g_start[d + 1];
    float ax = 0.f, ay = 0.f;
    #pragma unroll 2
    for (int i = i0 + eg; i < i1; i += 8) {
        int2 p = g_epack[i];
        float w = __int_as_float(p.y);
        __half2 sv = *reinterpret_cast<const __half2*>(&g_simT[p.x * 64 + 2 * l]);
        float2 f = __half22float2(sv);
        ax += w * f.x;
        ay += w * f.y;
    }
    __shared__ float sx[256], sy[256];
    sx[t] = ax; sy[t] = ay;
    __syncthreads();
    if (eg == 0) {
        float tx = 0.f, ty = 0.f;
        #pragma unroll
        for (int k = 0; k < 8; k++) { tx += sx[32 * k + l]; ty += sy[32 * k + l]; }
        int b0 = 2 * l;
        out[(size_t)b0 * D + d]       = ETA * g_gnorm[b0]     * tx;
        out[(size_t)(b0 + 1) * D + d] = ETA * g_gnorm[b0 + 1] * ty;
    }
}

// ---------------- launch -----------------------------------------------------
extern "C" void kernel_launch(void* const* d_in, const int* in_sizes, int n_in,
                              void* d_out, int out_size) {
    const float* H  = (const float*)d_in[0];   // [B,F]
    const float* G  = (const float*)d_in[1];   // [B,F]
    const float* SF = (const float*)d_in[2];   // [S,F]
    const float* ew = (const float*)d_in[3];   // [E]
    const int*   ed = (const int*)d_in[4];     // [E]
    const int*   es = (const int*)d_in[5];     // [E]
    float* out = (float*)d_out;

    int Bv = in_sizes[0] / FF;                 // 64
    int S  = in_sizes[2] / FF;                 // 8192
    int E  = in_sizes[3];                      // 500000
    int D  = out_size / Bv;                    // 1024
    int CH = (E + NBLK - 1) / NBLK;            // edges per partition block

    static int smem_set = 0;
    if (!smem_set) {
        cudaFuncSetAttribute(sim_kernel,
                             cudaFuncAttributeMaxDynamicSharedMemorySize,
                             SIM_SMEM);
        smem_set = 1;
    }

    prep_h_kernel<<<Bv, 128>>>(H, G);
    hist_kernel<<<NBLK, 1024>>>(ed, E, CH);
    scan_pre_kernel<<<8, 1024>>>();
    scan_kernel<<<1, 1024>>>();
    scat_kernel<<<NBLK, 1024>>>(ew, ed, es, E, CH);
    sim_kernel<<<S / 64, 256, SIM_SMEM>>>(SF);
    out_kernel<<<D, 256>>>(out, D);
}

// round 8
// speedup vs baseline: 2.9804x; 1.0018x over previous
#include <cuda_runtime.h>
#include <cuda_fp16.h>
#include <cuda_bf16.h>
#include <math.h>
#include <stdint.h>

// Shapes fixed by the dataset: B=64, F=512, S=8192, E=500000, D=1024.
#define BB    64
#define FF    512
#define S_MAX 8192
#define E_MAX 500000
#define D_MAX 1024
#define NBLK  296            // partition blocks for hist/scatter (2 blocks/SM)
#define EPSV  1e-8f
#define ETA   0.01f

// ---------------- device scratch (static: no allocations allowed) ------------
__device__ __nv_bfloat16 g_HnB[BB * FF];   // normalized heatmap, bf16 [b][f]
__device__ float  g_gnorm[BB];             // ||grad_b||
__device__ __half g_simT[S_MAX * BB];      // sim transposed [s][b], fp16
__device__ int    g_blkcnt[NBLK * D_MAX];  // per-block histograms -> local prefixes
__device__ int    g_cnt[D_MAX];            // per-disease totals
__device__ int    g_start[D_MAX + 1];      // bucket starts
__device__ int2   g_epack[E_MAX];          // (sign, weight-bits) bucketed by disease
__device__ int    g_tick = 0;              // decoupled-scan ticket (reset each run)

// ================= portable tensor-core helpers (sm_80+) =====================
__device__ __forceinline__ uint32_t smem_u32(const void* p) {
    uint32_t a;
    asm("{ .reg .u64 t; cvta.to.shared.u64 t, %1; cvt.u32.u64 %0, t; }"
        : "=r"(a) : "l"(p));
    return a;
}
#define LDSM_X4(r, addr)                                                       \
    asm volatile("ldmatrix.sync.aligned.m8n8.x4.shared.b16 {%0,%1,%2,%3}, [%4];" \
        : "=r"((r)[0]), "=r"((r)[1]), "=r"((r)[2]), "=r"((r)[3])               \
        : "r"(addr))
__device__ __forceinline__ void mma_bf16(float* c, const uint32_t* a,
                                         uint32_t b0, uint32_t b1) {
    asm volatile(
        "mma.sync.aligned.m16n8k16.row.col.f32.bf16.bf16.f32 "
        "{%0,%1,%2,%3}, {%4,%5,%6,%7}, {%8,%9}, {%0,%1,%2,%3};"
        : "+f"(c[0]), "+f"(c[1]), "+f"(c[2]), "+f"(c[3])
        : "r"(a[0]), "r"(a[1]), "r"(a[2]), "r"(a[3]), "r"(b0), "r"(b1));
}

// ---------------- K1: fused prep_h (blocks 0..7) + histogram (blocks 8+) -----
__global__ void __launch_bounds__(1024, 1)
combo1_kernel(const float* __restrict__ H,
              const float* __restrict__ G,
              const int* __restrict__ ed, int E, int CH) {
    __shared__ int h[D_MAX];               // hist branch
    __shared__ float wsh[8][4], wsg[8][4]; // prep branch
    __shared__ float sinvs[8];
    int t = threadIdx.x;                   // 1024

    if (blockIdx.x < 8) {
        // ---- prep: 8 H-rows per block, 128 threads per row ----
        int r  = t >> 7;                   // row group 0..7
        int tt = t & 127;
        int b  = blockIdx.x * 8 + r;       // 0..63
        float4 hv = reinterpret_cast<const float4*>(H + b * FF)[tt];
        float4 gv = reinterpret_cast<const float4*>(G + b * FF)[tt];
        float sh = hv.x * hv.x + hv.y * hv.y + hv.z * hv.z + hv.w * hv.w;
        float sg = gv.x * gv.x + gv.y * gv.y + gv.z * gv.z + gv.w * gv.w;
        #pragma unroll
        for (int o = 16; o > 0; o >>= 1) {
            sh += __shfl_down_sync(0xffffffffu, sh, o);
            sg += __shfl_down_sync(0xffffffffu, sg, o);
        }
        if ((tt & 31) == 0) { wsh[r][tt >> 5] = sh; wsg[r][tt >> 5] = sg; }
        __syncthreads();
        if (tt == 0) {
            float th = wsh[r][0] + wsh[r][1] + wsh[r][2] + wsh[r][3];
            float tg = wsg[r][0] + wsg[r][1] + wsg[r][2] + wsg[r][3];
            sinvs[r] = 1.0f / (sqrtf(th) + EPSV);
            g_gnorm[b] = sqrtf(tg);
        }
        __syncthreads();
        float inv = sinvs[r];
        __nv_bfloat162 p0 = __floats2bfloat162_rn(hv.x * inv, hv.y * inv);
        __nv_bfloat162 p1 = __floats2bfloat162_rn(hv.z * inv, hv.w * inv);
        uint2 u;
        u.x = *reinterpret_cast<uint32_t*>(&p0);
        u.y = *reinterpret_cast<uint32_t*>(&p1);
        reinterpret_cast<uint2*>(g_HnB)[b * 128 + tt] = u;
    } else {
        // ---- hist: privatized smem histogram ----
        int hb = blockIdx.x - 8;           // 0..NBLK-1
        h[t] = 0;
        __syncthreads();
        int e0 = hb * CH;
        int e1 = min(E, e0 + CH);
        for (int e = e0 + t; e < e1; e += 1024) atomicAdd(&h[ed[e]], 1);
        __syncthreads();
        g_blkcnt[hb * D_MAX + t] = h[t];
    }
}

// ---------------- K2: per-block prefixes + fused final scan ------------------
__global__ void __launch_bounds__(1024, 1) scan_pre_kernel() {
    int g  = blockIdx.x;           // 8 blocks, 128 diseases each
    int t  = threadIdx.x;          // 1024
    int dl = t & 127;
    int c  = t >> 7;               // 8 chunks over NBLK
    int d  = g * 128 + dl;
    const int per = (NBLK + 7) / 8;
    int b0 = c * per, b1 = min(NBLK, b0 + per);
    int sum = 0;
    for (int blk = b0; blk < b1; blk++) sum += g_blkcnt[blk * D_MAX + d];
    __shared__ int ch[8][128];
    ch[c][dl] = sum;
    __syncthreads();
    if (c == 0) {
        int r = 0;
        #pragma unroll
        for (int j = 0; j < 8; j++) { int v = ch[j][dl]; ch[j][dl] = r; r += v; }
        g_cnt[d] = r;
    }
    __syncthreads();
    int run = ch[c][dl];
    for (int blk = b0; blk < b1; blk++) {
        int idx = blk * D_MAX + d;
        int v = g_blkcnt[idx];
        g_blkcnt[idx] = run;       // within-disease exclusive prefix over blocks
        run += v;
    }

    // ---- decoupled final scan: last-arriving block scans g_cnt -> g_start ---
    __shared__ int is_last;
    __threadfence();
    if (t == 0) is_last = (atomicAdd(&g_tick, 1) == gridDim.x - 1) ? 1 : 0;
    __syncthreads();
    if (!is_last) return;

    __shared__ int wtot[32];
    int v = g_cnt[t];
    int l = t & 31, w = t >> 5;
    int inc = v;
    #pragma unroll
    for (int o = 1; o < 32; o <<= 1) {
        int n = __shfl_up_sync(0xffffffffu, inc, o);
        if (l >= o) inc += n;
    }
    if (l == 31) wtot[w] = inc;
    __syncthreads();
    if (w == 0) {
        int x = wtot[l];
        #pragma unroll
        for (int o = 1; o < 32; o <<= 1) {
            int n = __shfl_up_sync(0xffffffffu, x, o);
            if (l >= o) x += n;
        }
        wtot[l] = x;               // inclusive warp totals
    }
    __syncthreads();
    int base = (w > 0) ? wtot[w - 1] : 0;
    g_start[t + 1] = base + inc;
    if (t == 0) { g_start[0] = 0; g_tick = 0; }   // reset ticket for replay
}

// ---------------- K3: deterministic-offset scatter (smem cursors) -----------
__global__ void __launch_bounds__(1024, 1)
scat_kernel(const float* __restrict__ ew,
            const int* __restrict__ ed,
            const int* __restrict__ es, int E, int CH) {
    __shared__ int cur[D_MAX];
    int t = threadIdx.x;           // 1024
    cur[t] = g_blkcnt[blockIdx.x * D_MAX + t] + g_start[t];
    __syncthreads();
    int e0 = blockIdx.x * CH;
    int e1 = min(E, e0 + CH);
    for (int e = e0 + t; e < e1; e += 1024) {
        int d = ed[e];
        int pos = atomicAdd(&cur[d], 1);
        g_epack[pos] = make_int2(es[e], __float_as_int(ew[e]));
    }
}

// ---------------- K4: sim via HMMA (mma.sync bf16) ---------------------------
// Per block: M=64 signs x N=64 batch x K=512. A = raw S tile bf16, B = Hn bf16,
// both at 1040-byte row pitch (conflict-free ldmatrix). 8 warps, each 16m x 32n.
// Epilogue: sim = dot*(0.5*sinv_s) + 0.5 -> fp16 g_simT.
#define APITCH   1040                       // bytes per 512-bf16 row (+16 pad)
#define SIM_A_OFF 0
#define SIM_B_OFF (64 * APITCH)
#define SIM_SMEM  (128 * APITCH)            // 133120 B

__global__ void __launch_bounds__(256, 1) sim_kernel(const float* __restrict__ SF) {
    extern __shared__ char sm[];
    __shared__ float s_sumsq[64];
    __shared__ float s_sinv[64];
    uint32_t smA = smem_u32(sm) + SIM_A_OFF;
    uint32_t smB = smem_u32(sm) + SIM_B_OFF;
    int t   = threadIdx.x;         // 256
    int wid = t >> 5;
    int lid = t & 31;
    int s0  = blockIdx.x * 64;

    if (t < 64) s_sumsq[t] = 0.0f;
    __syncthreads();

    // Stage A: S tile [64 rows][512 f] fp32 -> bf16, pitch 1040. Fused norms.
    #pragma unroll 4
    for (int i = t; i < 64 * 128; i += 256) {
        int row = i >> 7;
        int q   = i & 127;
        float4 v = reinterpret_cast<const float4*>(SF)[(size_t)(s0 + row) * 128 + q];
        float sq = v.x * v.x + v.y * v.y + v.z * v.z + v.w * v.w;
        #pragma unroll
        for (int o = 16; o > 0; o >>= 1) sq += __shfl_down_sync(0xffffffffu, sq, o);
        if (lid == 0) atomicAdd(&s_sumsq[row], sq);
        __nv_bfloat162 b0 = __floats2bfloat162_rn(v.x, v.y);
        __nv_bfloat162 b1 = __floats2bfloat162_rn(v.z, v.w);
        uint2 u;
        u.x = *reinterpret_cast<uint32_t*>(&b0);
        u.y = *reinterpret_cast<uint32_t*>(&b1);
        *reinterpret_cast<uint2*>(sm + SIM_A_OFF + row * APITCH + q * 8) = u;
    }
    // Stage B: Hn [64 rows][512 f] bf16 -> pitch 1040.
    #pragma unroll 4
    for (int i = t; i < 64 * 64; i += 256) {   // 16B chunks
        int row = i >> 6;
        int c16 = i & 63;
        uint4 u = reinterpret_cast<const uint4*>(g_HnB)[row * 64 + c16];
        *reinterpret_cast<uint4*>(sm + SIM_B_OFF + row * APITCH + c16 * 16) = u;
    }
    __syncthreads();
    if (t < 64) s_sinv[t] = 0.5f / (sqrtf(s_sumsq[t]) + EPSV);

    // Warp tile: m0 = 16*(wid>>1), n0 = 32*(wid&1). 4 n8-tiles per warp.
    int m0 = (wid >> 1) * 16;
    int n0 = (wid & 1) * 32;
    float c[16];
    #pragma unroll
    for (int j = 0; j < 16; j++) c[j] = 0.0f;

    // ldmatrix lane addresses (constant across k except k offset)
    uint32_t aBase = smA + (uint32_t)(m0 + (lid & 15)) * APITCH + ((lid >> 4) << 4);
    int brow = ((lid >> 4) << 3) + (lid & 7);
    uint32_t kofs = (((lid >> 3) & 1) << 4);
    uint32_t bBase0 = smB + (uint32_t)(n0 + brow) * APITCH + kofs;
    uint32_t bBase1 = smB + (uint32_t)(n0 + 16 + brow) * APITCH + kofs;
    __syncthreads();

    #pragma unroll 4
    for (int k = 0; k < FF; k += 16) {
        uint32_t a[4], b[8];
        LDSM_X4(a, aBase + k * 2);
        LDSM_X4(b, bBase0 + k * 2);
        LDSM_X4(b + 4, bBase1 + k * 2);
        mma_bf16(c + 0,  a, b[0], b[1]);
        mma_bf16(c + 4,  a, b[2], b[3]);
        mma_bf16(c + 8,  a, b[4], b[5]);
        mma_bf16(c + 12, a, b[6], b[7]);
    }

    // Epilogue: thread holds rows r0=m0+lid/4, r1=r0+8; cols 2*(lid&3) per tile.
    int r0 = m0 + (lid >> 2);
    int r1 = r0 + 8;
    int cb = 2 * (lid & 3);
    float sc0 = s_sinv[r0];
    float sc1 = s_sinv[r1];
    #pragma unroll
    for (int nt = 0; nt < 4; nt++) {
        int col = n0 + nt * 8 + cb;
        __half2 h0 = __floats2half2_rn(c[nt * 4 + 0] * sc0 + 0.5f,
                                       c[nt * 4 + 1] * sc0 + 0.5f);
        __half2 h1 = __floats2half2_rn(c[nt * 4 + 2] * sc1 + 0.5f,
                                       c[nt * 4 + 3] * sc1 + 0.5f);
        *reinterpret_cast<__half2*>(&g_simT[(size_t)(s0 + r0) * 64 + col]) = h0;
        *reinterpret_cast<__half2*>(&g_simT[(size_t)(s0 + r1) * 64 + col]) = h1;
    }
}

// ---------------- K5: per-disease gather-reduce -> out -----------------------
__global__ void __launch_bounds__(256) out_kernel(float* __restrict__ out, int D) {
    int d  = blockIdx.x;
    int t  = threadIdx.x;             // 256
    int l  = t & 31;
    int eg = t >> 5;                  // 0..7
    int i0 = g_start[d];
    int i1 = g_start[d + 1];
    float ax = 0.f, ay = 0.f;
    #pragma unroll 2
    for (int i = i0 + eg; i < i1; i += 8) {
        int2 p = g_epack[i];
        float w = __int_as_float(p.y);
        __half2 sv = *reinterpret_cast<const __half2*>(&g_simT[p.x * 64 + 2 * l]);
        float2 f = __half22float2(sv);
        ax += w * f.x;
        ay += w * f.y;
    }
    __shared__ float sx[256], sy[256];
    sx[t] = ax; sy[t] = ay;
    __syncthreads();
    if (eg == 0) {
        float tx = 0.f, ty = 0.f;
        #pragma unroll
        for (int k = 0; k < 8; k++) { tx += sx[32 * k + l]; ty += sy[32 * k + l]; }
        int b0 = 2 * l;
        out[(size_t)b0 * D + d]       = ETA * g_gnorm[b0]     * tx;
        out[(size_t)(b0 + 1) * D + d] = ETA * g_gnorm[b0 + 1] * ty;
    }
}

// ---------------- launch: single stream, 5 kernels ---------------------------
extern "C" void kernel_launch(void* const* d_in, const int* in_sizes, int n_in,
                              void* d_out, int out_size) {
    const float* H  = (const float*)d_in[0];   // [B,F]
    const float* G  = (const float*)d_in[1];   // [B,F]
    const float* SF = (const float*)d_in[2];   // [S,F]
    const float* ew = (const float*)d_in[3];   // [E]
    const int*   ed = (const int*)d_in[4];     // [E]
    const int*   es = (const int*)d_in[5];     // [E]
    float* out = (float*)d_out;

    int S  = in_sizes[2] / FF;                 // 8192
    int E  = in_sizes[3];                      // 500000
    int D  = 1024;
    int CH = (E + NBLK - 1) / NBLK;            // edges per partition block

    static int smem_set = 0;
    if (!smem_set) {
        cudaFuncSetAttribute(sim_kernel,
                             cudaFuncAttributeMaxDynamicSharedMemorySize,
                             SIM_SMEM);
        smem_set = 1;
    }

    combo1_kernel<<<NBLK + 8, 1024>>>(H, G, ed, E, CH);
    scan_pre_kernel<<<8, 1024>>>();
    scat_kernel<<<NBLK, 1024>>>(ew, ed, es, E, CH);
    sim_kernel<<<S / 64, 256, SIM_SMEM>>>(SF);
    out_kernel<<<D, 256>>>(out, D);
}

// round 9
// speedup vs baseline: 3.3082x; 1.1100x over previous
#include <cuda_runtime.h>
#include <cuda_fp16.h>
#include <cuda_bf16.h>
#include <math.h>
#include <stdint.h>

// Shapes fixed by the dataset: B=64, F=512, S=8192, E=500000, D=1024.
#define BB    64
#define FF    512
#define S_MAX 8192
#define E_MAX 500000
#define D_MAX 1024
#define NBLK  296            // partition blocks for hist/scatter (2 blocks/SM)
#define EPSV  1e-8f
#define ETA   0.01f

// ---------------- device scratch (static: no allocations allowed) ------------
__device__ __nv_bfloat16 g_HnB[BB * FF];   // normalized heatmap, bf16 [b][f]
__device__ float  g_gnorm[BB];             // ||grad_b||
__device__ __half g_simT[S_MAX * BB];      // sim transposed [s][b], fp16
__device__ int    g_blkcnt[NBLK * D_MAX];  // per-block histograms -> local prefixes
__device__ int    g_cnt[D_MAX];            // per-disease totals
__device__ int    g_start[D_MAX + 1];      // bucket starts
__device__ int2   g_epack[E_MAX];          // (sign, weight-bits) bucketed by disease
__device__ int    g_tick = 0;              // decoupled-scan ticket (reset each run)

// ================= portable tensor-core helpers (sm_80+) =====================
__device__ __forceinline__ uint32_t smem_u32(const void* p) {
    uint32_t a;
    asm("{ .reg .u64 t; cvta.to.shared.u64 t, %1; cvt.u32.u64 %0, t; }"
        : "=r"(a) : "l"(p));
    return a;
}
#define LDSM_X4(r, addr)                                                       \
    asm volatile("ldmatrix.sync.aligned.m8n8.x4.shared.b16 {%0,%1,%2,%3}, [%4];" \
        : "=r"((r)[0]), "=r"((r)[1]), "=r"((r)[2]), "=r"((r)[3])               \
        : "r"(addr))
__device__ __forceinline__ void mma_bf16(float* c, const uint32_t* a,
                                         uint32_t b0, uint32_t b1) {
    asm volatile(
        "mma.sync.aligned.m16n8k16.row.col.f32.bf16.bf16.f32 "
        "{%0,%1,%2,%3}, {%4,%5,%6,%7}, {%8,%9}, {%0,%1,%2,%3};"
        : "+f"(c[0]), "+f"(c[1]), "+f"(c[2]), "+f"(c[3])
        : "r"(a[0]), "r"(a[1]), "r"(a[2]), "r"(a[3]), "r"(b0), "r"(b1));
}

// ---------------- K1: fused prep_h (blocks 0..7) + histogram (blocks 8+) -----
__global__ void __launch_bounds__(1024, 1)
combo1_kernel(const float* __restrict__ H,
              const float* __restrict__ G,
              const int* __restrict__ ed, int E, int CH) {
    __shared__ int h[D_MAX];               // hist branch
    __shared__ float wsh[8][4], wsg[8][4]; // prep branch
    __shared__ float sinvs[8];
    int t = threadIdx.x;                   // 1024

    if (blockIdx.x < 8) {
        // ---- prep: 8 H-rows per block, 128 threads per row ----
        int r  = t >> 7;                   // row group 0..7
        int tt = t & 127;
        int b  = blockIdx.x * 8 + r;       // 0..63
        float4 hv = reinterpret_cast<const float4*>(H + b * FF)[tt];
        float4 gv = reinterpret_cast<const float4*>(G + b * FF)[tt];
        float sh = hv.x * hv.x + hv.y * hv.y + hv.z * hv.z + hv.w * hv.w;
        float sg = gv.x * gv.x + gv.y * gv.y + gv.z * gv.z + gv.w * gv.w;
        #pragma unroll
        for (int o = 16; o > 0; o >>= 1) {
            sh += __shfl_down_sync(0xffffffffu, sh, o);
            sg += __shfl_down_sync(0xffffffffu, sg, o);
        }
        if ((tt & 31) == 0) { wsh[r][tt >> 5] = sh; wsg[r][tt >> 5] = sg; }
        __syncthreads();
        if (tt == 0) {
            float th = wsh[r][0] + wsh[r][1] + wsh[r][2] + wsh[r][3];
            float tg = wsg[r][0] + wsg[r][1] + wsg[r][2] + wsg[r][3];
            sinvs[r] = 1.0f / (sqrtf(th) + EPSV);
            g_gnorm[b] = sqrtf(tg);
        }
        __syncthreads();
        float inv = sinvs[r];
        __nv_bfloat162 p0 = __floats2bfloat162_rn(hv.x * inv, hv.y * inv);
        __nv_bfloat162 p1 = __floats2bfloat162_rn(hv.z * inv, hv.w * inv);
        uint2 u;
        u.x = *reinterpret_cast<uint32_t*>(&p0);
        u.y = *reinterpret_cast<uint32_t*>(&p1);
        reinterpret_cast<uint2*>(g_HnB)[b * 128 + tt] = u;
    } else {
        // ---- hist: privatized smem histogram ----
        int hb = blockIdx.x - 8;           // 0..NBLK-1
        h[t] = 0;
        __syncthreads();
        int e0 = hb * CH;
        int e1 = min(E, e0 + CH);
        for (int e = e0 + t; e < e1; e += 1024) atomicAdd(&h[ed[e]], 1);
        __syncthreads();
        g_blkcnt[hb * D_MAX + t] = h[t];
    }
}

// ---------------- K2: per-block prefixes + fused final scan ------------------
__global__ void __launch_bounds__(1024, 1) scan_pre_kernel() {
    int g  = blockIdx.x;           // 8 blocks, 128 diseases each
    int t  = threadIdx.x;          // 1024
    int dl = t & 127;
    int c  = t >> 7;               // 8 chunks over NBLK
    int d  = g * 128 + dl;
    const int per = (NBLK + 7) / 8;
    int b0 = c * per, b1 = min(NBLK, b0 + per);
    int sum = 0;
    for (int blk = b0; blk < b1; blk++) sum += g_blkcnt[blk * D_MAX + d];
    __shared__ int ch[8][128];
    ch[c][dl] = sum;
    __syncthreads();
    if (c == 0) {
        int r = 0;
        #pragma unroll
        for (int j = 0; j < 8; j++) { int v = ch[j][dl]; ch[j][dl] = r; r += v; }
        g_cnt[d] = r;
    }
    __syncthreads();
    int run = ch[c][dl];
    for (int blk = b0; blk < b1; blk++) {
        int idx = blk * D_MAX + d;
        int v = g_blkcnt[idx];
        g_blkcnt[idx] = run;       // within-disease exclusive prefix over blocks
        run += v;
    }

    // ---- decoupled final scan: last-arriving block scans g_cnt -> g_start ---
    __shared__ int is_last;
    __threadfence();
    if (t == 0) is_last = (atomicAdd(&g_tick, 1) == gridDim.x - 1) ? 1 : 0;
    __syncthreads();
    if (!is_last) return;

    __shared__ int wtot[32];
    int v = g_cnt[t];
    int l = t & 31, w = t >> 5;
    int inc = v;
    #pragma unroll
    for (int o = 1; o < 32; o <<= 1) {
        int n = __shfl_up_sync(0xffffffffu, inc, o);
        if (l >= o) inc += n;
    }
    if (l == 31) wtot[w] = inc;
    __syncthreads();
    if (w == 0) {
        int x = wtot[l];
        #pragma unroll
        for (int o = 1; o < 32; o <<= 1) {
            int n = __shfl_up_sync(0xffffffffu, x, o);
            if (l >= o) x += n;
        }
        wtot[l] = x;               // inclusive warp totals
    }
    __syncthreads();
    int base = (w > 0) ? wtot[w - 1] : 0;
    g_start[t + 1] = base + inc;
    if (t == 0) { g_start[0] = 0; g_tick = 0; }   // reset ticket for replay
}

// ---------------- K3: deterministic-offset scatter (smem cursors) -----------
__global__ void __launch_bounds__(1024, 1)
scat_kernel(const float* __restrict__ ew,
            const int* __restrict__ ed,
            const int* __restrict__ es, int E, int CH) {
    __shared__ int cur[D_MAX];
    int t = threadIdx.x;           // 1024
    cur[t] = g_blkcnt[blockIdx.x * D_MAX + t] + g_start[t];
    __syncthreads();
    int e0 = blockIdx.x * CH;
    int e1 = min(E, e0 + CH);
    for (int e = e0 + t; e < e1; e += 1024) {
        int d = ed[e];
        int pos = atomicAdd(&cur[d], 1);
        g_epack[pos] = make_int2(es[e], __float_as_int(ew[e]));
    }
}

// ---------------- K4: sim via HMMA (mma.sync bf16), MLP-staged ---------------
// Per block: M=64 signs x N=64 batch x K=512, 512 threads (16 warps).
// Staging is pure LDG->cvt->STS (unrolled, high MLP); row sumsq computed in a
// second pass over the bf16 smem tile. Warp tile 16m x 16n.
// Epilogue: sim = dot*(0.5*sinv_s) + 0.5 -> fp16 g_simT.
#define APITCH   1040                       // bytes per 512-bf16 row (+16 pad)
#define SIM_A_OFF 0
#define SIM_B_OFF (64 * APITCH)
#define SIM_SMEM  (128 * APITCH)            // 133120 B

__global__ void __launch_bounds__(512, 1) sim_kernel(const float* __restrict__ SF) {
    extern __shared__ char sm[];
    __shared__ float s_sinv[64];
    uint32_t smA = smem_u32(sm) + SIM_A_OFF;
    uint32_t smB = smem_u32(sm) + SIM_B_OFF;
    int t   = threadIdx.x;         // 512
    int wid = t >> 5;              // 0..15
    int lid = t & 31;
    int s0  = blockIdx.x * 64;

    // Stage A: S tile [64 rows][512 f] fp32 -> bf16, pitch 1040. Pure streaming.
    // i = t + 512*j: q = t&127 fixed, row = (t>>7) + 4*j  (coalesced, MLP=8).
    {
        int q   = t & 127;
        int rr  = t >> 7;
        #pragma unroll 8
        for (int j = 0; j < 16; j++) {
            int row = rr + 4 * j;
            float4 v = reinterpret_cast<const float4*>(SF)[(size_t)(s0 + row) * 128 + q];
            __nv_bfloat162 b0 = __floats2bfloat162_rn(v.x, v.y);
            __nv_bfloat162 b1 = __floats2bfloat162_rn(v.z, v.w);
            uint2 u;
            u.x = *reinterpret_cast<uint32_t*>(&b0);
            u.y = *reinterpret_cast<uint32_t*>(&b1);
            *reinterpret_cast<uint2*>(sm + SIM_A_OFF + row * APITCH + q * 8) = u;
        }
    }
    // Stage B: Hn [64 rows][512 f] bf16 -> pitch 1040 (8x 16B chunks/thread).
    #pragma unroll 8
    for (int i = t; i < 64 * 64; i += 512) {
        int row = i >> 6;
        int c16 = i & 63;
        uint4 u = reinterpret_cast<const uint4*>(g_HnB)[row * 64 + c16];
        *reinterpret_cast<uint4*>(sm + SIM_B_OFF + row * APITCH + c16 * 16) = u;
    }
    __syncthreads();

    // Second pass: per-row sumsq from staged bf16 (warp w -> rows 4w..4w+3).
    {
        #pragma unroll
        for (int rr = 0; rr < 4; rr++) {
            int row = wid * 4 + rr;
            const uint32_t* rp = reinterpret_cast<const uint32_t*>(sm + SIM_A_OFF + row * APITCH);
            float sq = 0.f;
            #pragma unroll
            for (int j = 0; j < 8; j++) {
                uint32_t pk = rp[lid + 32 * j];
                __nv_bfloat162 bb = *reinterpret_cast<__nv_bfloat162*>(&pk);
                float2 f = __bfloat1622float2(bb);
                sq += f.x * f.x + f.y * f.y;
            }
            #pragma unroll
            for (int o = 16; o > 0; o >>= 1) sq += __shfl_down_sync(0xffffffffu, sq, o);
            if (lid == 0) s_sinv[row] = 0.5f / (sqrtf(sq) + EPSV);
        }
    }
    __syncthreads();

    // Warp tile: m0 = 16*(wid>>2), n0 = 16*(wid&3). 2 n8-tiles per warp.
    int m0 = (wid >> 2) * 16;
    int n0 = (wid & 3) * 16;
    float c[8];
    #pragma unroll
    for (int j = 0; j < 8; j++) c[j] = 0.0f;

    uint32_t aBase = smA + (uint32_t)(m0 + (lid & 15)) * APITCH + ((lid >> 4) << 4);
    int brow = ((lid >> 4) << 3) + (lid & 7);
    uint32_t kofs = (((lid >> 3) & 1) << 4);
    uint32_t bBase = smB + (uint32_t)(n0 + brow) * APITCH + kofs;

    #pragma unroll 8
    for (int k = 0; k < FF; k += 16) {
        uint32_t a[4], b[4];
        LDSM_X4(a, aBase + k * 2);
        LDSM_X4(b, bBase + k * 2);
        mma_bf16(c + 0, a, b[0], b[1]);
        mma_bf16(c + 4, a, b[2], b[3]);
    }

    // Epilogue: thread holds rows r0=m0+lid/4, r1=r0+8; cols 2*(lid&3) per tile.
    int r0 = m0 + (lid >> 2);
    int r1 = r0 + 8;
    int cb = 2 * (lid & 3);
    float sc0 = s_sinv[r0];
    float sc1 = s_sinv[r1];
    #pragma unroll
    for (int nt = 0; nt < 2; nt++) {
        int col = n0 + nt * 8 + cb;
        __half2 h0 = __floats2half2_rn(c[nt * 4 + 0] * sc0 + 0.5f,
                                       c[nt * 4 + 1] * sc0 + 0.5f);
        __half2 h1 = __floats2half2_rn(c[nt * 4 + 2] * sc1 + 0.5f,
                                       c[nt * 4 + 3] * sc1 + 0.5f);
        *reinterpret_cast<__half2*>(&g_simT[(size_t)(s0 + r0) * 64 + col]) = h0;
        *reinterpret_cast<__half2*>(&g_simT[(size_t)(s0 + r1) * 64 + col]) = h1;
    }
}

// ---------------- K5: per-disease gather-reduce -> out -----------------------
__global__ void __launch_bounds__(256) out_kernel(float* __restrict__ out, int D) {
    int d  = blockIdx.x;
    int t  = threadIdx.x;             // 256
    int l  = t & 31;
    int eg = t >> 5;                  // 0..7
    int i0 = g_start[d];
    int i1 = g_start[d + 1];
    float ax = 0.f, ay = 0.f;
    #pragma unroll 2
    for (int i = i0 + eg; i < i1; i += 8) {
        int2 p = g_epack[i];
        float w = __int_as_float(p.y);
        __half2 sv = *reinterpret_cast<const __half2*>(&g_simT[p.x * 64 + 2 * l]);
        float2 f = __half22float2(sv);
        ax += w * f.x;
        ay += w * f.y;
    }
    __shared__ float sx[256], sy[256];
    sx[t] = ax; sy[t] = ay;
    __syncthreads();
    if (eg == 0) {
        float tx = 0.f, ty = 0.f;
        #pragma unroll
        for (int k = 0; k < 8; k++) { tx += sx[32 * k + l]; ty += sy[32 * k + l]; }
        int b0 = 2 * l;
        out[(size_t)b0 * D + d]       = ETA * g_gnorm[b0]     * tx;
        out[(size_t)(b0 + 1) * D + d] = ETA * g_gnorm[b0 + 1] * ty;
    }
}

// ---------------- launch: single stream, 5 kernels ---------------------------
extern "C" void kernel_launch(void* const* d_in, const int* in_sizes, int n_in,
                              void* d_out, int out_size) {
    const float* H  = (const float*)d_in[0];   // [B,F]
    const float* G  = (const float*)d_in[1];   // [B,F]
    const float* SF = (const float*)d_in[2];   // [S,F]
    const float* ew = (const float*)d_in[3];   // [E]
    const int*   ed = (const int*)d_in[4];     // [E]
    const int*   es = (const int*)d_in[5];     // [E]
    float* out = (float*)d_out;

    int S  = in_sizes[2] / FF;                 // 8192
    int E  = in_sizes[3];                      // 500000
    int D  = 1024;
    int CH = (E + NBLK - 1) / NBLK;            // edges per partition block

    static int smem_set = 0;
    if (!smem_set) {
        cudaFuncSetAttribute(sim_kernel,
                             cudaFuncAttributeMaxDynamicSharedMemorySize,
                             SIM_SMEM);
        smem_set = 1;
    }

    combo1_kernel<<<NBLK + 8, 1024>>>(H, G, ed, E, CH);
    scan_pre_kernel<<<8, 1024>>>();
    scat_kernel<<<NBLK, 1024>>>(ew, ed, es, E, CH);
    sim_kernel<<<S / 64, 512, SIM_SMEM>>>(SF);
    out_kernel<<<D, 256>>>(out, D);
}

// round 11
// speedup vs baseline: 3.4463x; 1.0417x over previous
#include <cuda_runtime.h>
#include <cuda_fp16.h>
#include <cuda_bf16.h>
#include <math.h>
#include <stdint.h>

// Shapes fixed by the dataset: B=64, F=512, S=8192, E=500000, D=1024.
#define BB    64
#define FF    512
#define S_MAX 8192
#define E_MAX 500000
#define D_MAX 1024
#define NBLK  296            // edge partition blocks (hist & scat must match)
#define NSIM  256            // sim tiles: 8192 / 32
#define EPSV  1e-8f
#define ETA   0.01f

// ---------------- device scratch (static: no allocations allowed) ------------
__device__ __nv_bfloat16 g_HnB[BB * FF];   // normalized heatmap, bf16 [b][f]
__device__ float  g_gnorm[BB];             // ||grad_b||
__device__ __half g_simT[S_MAX * BB];      // sim transposed [s][b], fp16
__device__ int    g_blkcnt[NBLK * D_MAX];  // per-block histograms -> local prefixes
__device__ int    g_cnt[D_MAX];            // per-disease totals
__device__ int    g_start[D_MAX + 1];      // bucket starts
__device__ int2   g_epack[E_MAX];          // (sign, weight-bits) bucketed by disease
__device__ int    g_tick = 0;              // decoupled-scan ticket (reset each run)

// ================= portable tensor-core helpers (sm_80+) =====================
__device__ __forceinline__ uint32_t smem_u32(const void* p) {
    uint32_t a;
    asm("{ .reg .u64 t; cvta.to.shared.u64 t, %1; cvt.u32.u64 %0, t; }"
        : "=r"(a) : "l"(p));
    return a;
}
#define LDSM_X4(r, addr)                                                       \
    asm volatile("ldmatrix.sync.aligned.m8n8.x4.shared.b16 {%0,%1,%2,%3}, [%4];" \
        : "=r"((r)[0]), "=r"((r)[1]), "=r"((r)[2]), "=r"((r)[3])               \
        : "r"(addr))
#define LDSM_X2(r0, r1, addr)                                                  \
    asm volatile("ldmatrix.sync.aligned.m8n8.x2.shared.b16 {%0,%1}, [%2];"     \
        : "=r"(r0), "=r"(r1) : "r"(addr))
__device__ __forceinline__ void mma_bf16(float* c, const uint32_t* a,
                                         uint32_t b0, uint32_t b1) {
    asm volatile(
        "mma.sync.aligned.m16n8k16.row.col.f32.bf16.bf16.f32 "
        "{%0,%1,%2,%3}, {%4,%5,%6,%7}, {%8,%9}, {%0,%1,%2,%3};"
        : "+f"(c[0]), "+f"(c[1]), "+f"(c[2]), "+f"(c[3])
        : "r"(a[0]), "r"(a[1]), "r"(a[2]), "r"(a[3]), "r"(b0), "r"(b1));
}

// ---------------- K1: fused prep_h (blocks 0..7) + histogram (blocks 8+) -----
__global__ void __launch_bounds__(1024, 1)
combo1_kernel(const float* __restrict__ H,
              const float* __restrict__ G,
              const int* __restrict__ ed, int E, int CH) {
    __shared__ int h[D_MAX];               // hist branch
    __shared__ float wsh[8][4], wsg[8][4]; // prep branch
    __shared__ float sinvs[8];
    int t = threadIdx.x;                   // 1024

    if (blockIdx.x < 8) {
        int r  = t >> 7;                   // row group 0..7
        int tt = t & 127;
        int b  = blockIdx.x * 8 + r;       // 0..63
        float4 hv = reinterpret_cast<const float4*>(H + b * FF)[tt];
        float4 gv = reinterpret_cast<const float4*>(G + b * FF)[tt];
        float sh = hv.x * hv.x + hv.y * hv.y + hv.z * hv.z + hv.w * hv.w;
        float sg = gv.x * gv.x + gv.y * gv.y + gv.z * gv.z + gv.w * gv.w;
        #pragma unroll
        for (int o = 16; o > 0; o >>= 1) {
            sh += __shfl_down_sync(0xffffffffu, sh, o);
            sg += __shfl_down_sync(0xffffffffu, sg, o);
        }
        if ((tt & 31) == 0) { wsh[r][tt >> 5] = sh; wsg[r][tt >> 5] = sg; }
        __syncthreads();
        if (tt == 0) {
            float th = wsh[r][0] + wsh[r][1] + wsh[r][2] + wsh[r][3];
            float tg = wsg[r][0] + wsg[r][1] + wsg[r][2] + wsg[r][3];
            sinvs[r] = 1.0f / (sqrtf(th) + EPSV);
            g_gnorm[b] = sqrtf(tg);
        }
        __syncthreads();
        float inv = sinvs[r];
        __nv_bfloat162 p0 = __floats2bfloat162_rn(hv.x * inv, hv.y * inv);
        __nv_bfloat162 p1 = __floats2bfloat162_rn(hv.z * inv, hv.w * inv);
        uint2 u;
        u.x = *reinterpret_cast<uint32_t*>(&p0);
        u.y = *reinterpret_cast<uint32_t*>(&p1);
        reinterpret_cast<uint2*>(g_HnB)[b * 128 + tt] = u;
    } else {
        int hb = blockIdx.x - 8;           // 0..NBLK-1
        h[t] = 0;
        __syncthreads();
        int e0 = hb * CH;
        int e1 = min(E, e0 + CH);
        for (int e = e0 + t; e < e1; e += 1024) atomicAdd(&h[ed[e]], 1);
        __syncthreads();
        g_blkcnt[hb * D_MAX + t] = h[t];
    }
}

// ---------------- K2: per-block prefixes + fused final scan ------------------
__global__ void __launch_bounds__(1024, 1) scan_pre_kernel() {
    int g  = blockIdx.x;           // 8 blocks, 128 diseases each
    int t  = threadIdx.x;          // 1024
    int dl = t & 127;
    int c  = t >> 7;               // 8 chunks over NBLK
    int d  = g * 128 + dl;
    const int per = (NBLK + 7) / 8;
    int b0 = c * per, b1 = min(NBLK, b0 + per);
    int sum = 0;
    for (int blk = b0; blk < b1; blk++) sum += g_blkcnt[blk * D_MAX + d];
    __shared__ int ch[8][128];
    ch[c][dl] = sum;
    __syncthreads();
    if (c == 0) {
        int r = 0;
        #pragma unroll
        for (int j = 0; j < 8; j++) { int v = ch[j][dl]; ch[j][dl] = r; r += v; }
        g_cnt[d] = r;
    }
    __syncthreads();
    int run = ch[c][dl];
    for (int blk = b0; blk < b1; blk++) {
        int idx = blk * D_MAX + d;
        int v = g_blkcnt[idx];
        g_blkcnt[idx] = run;       // within-disease exclusive prefix over blocks
        run += v;
    }

    // ---- decoupled final scan: last-arriving block scans g_cnt -> g_start ---
    __shared__ int is_last;
    __threadfence();
    if (t == 0) is_last = (atomicAdd(&g_tick, 1) == gridDim.x - 1) ? 1 : 0;
    __syncthreads();
    if (!is_last) return;

    __shared__ int wtot[32];
    int v = g_cnt[t];
    int l = t & 31, w = t >> 5;
    int inc = v;
    #pragma unroll
    for (int o = 1; o < 32; o <<= 1) {
        int n = __shfl_up_sync(0xffffffffu, inc, o);
        if (l >= o) inc += n;
    }
    if (l == 31) wtot[w] = inc;
    __syncthreads();
    if (w == 0) {
        int x = wtot[l];
        #pragma unroll
        for (int o = 1; o < 32; o <<= 1) {
            int n = __shfl_up_sync(0xffffffffu, x, o);
            if (l >= o) x += n;
        }
        wtot[l] = x;               // inclusive warp totals
    }
    __syncthreads();
    int base = (w > 0) ? wtot[w - 1] : 0;
    g_start[t + 1] = base + inc;
    if (t == 0) { g_start[0] = 0; g_tick = 0; }   // reset ticket for replay
}

// ---------------- K3: FUSED scatter + sim (independent chains, one launch) ---
// 512 threads, 2 blocks/SM (regs<=64, smem ~98KB). Interleaved block mapping:
// odd blocks (first 512) are sim tiles, so wave 1 runs ~148 of each kind.
// sim tile: M=32 signs x N=64 batch x K=512; warp tile 16x8 (16 warps).
#define APITCH    1040                      // bytes per 512-bf16 row (+16 pad)
#define FS_A_OFF  0
#define FS_B_OFF  (32 * APITCH)
#define FS_SMEM   (96 * APITCH)             // 99840 B

__global__ void __launch_bounds__(512, 2)
fused_kernel(const float* __restrict__ SF,
             const float* __restrict__ ew,
             const int* __restrict__ ed,
             const int* __restrict__ es, int E, int CH) {
    extern __shared__ char sm[];
    int t   = threadIdx.x;         // 512
    int bid = blockIdx.x;

    bool is_sim = (bid & 1) && ((bid >> 1) < NSIM);
    if (!is_sim) {
        // ================== scat branch ==================
        int scid = bid - min((bid + 1) >> 1, NSIM);   // 0..NBLK-1
        int* cur = reinterpret_cast<int*>(sm);
        cur[t]       = g_blkcnt[scid * D_MAX + t]       + g_start[t];
        cur[t + 512] = g_blkcnt[scid * D_MAX + t + 512] + g_start[t + 512];
        __syncthreads();
        int e0 = scid * CH;
        int e1 = min(E, e0 + CH);
        for (int e = e0 + t; e < e1; e += 512) {
            int d = ed[e];
            int pos = atomicAdd(&cur[d], 1);
            g_epack[pos] = make_int2(es[e], __float_as_int(ew[e]));
        }
        return;
    }

    // ================== sim branch ==================
    int sid = bid >> 1;            // 0..NSIM-1
    int s0  = sid * 32;
    int wid = t >> 5;              // 0..15
    int lid = t & 31;
    __shared__ float s_sinv[32];
    uint32_t smA = smem_u32(sm) + FS_A_OFF;
    uint32_t smB = smem_u32(sm) + FS_B_OFF;

    // Stage A: S tile [32 rows][512 f] fp32 -> bf16, pitch 1040 (MLP 8).
    {
        int q  = t & 127;
        int rr = t >> 7;           // 0..3
        #pragma unroll 8
        for (int j = 0; j < 8; j++) {
            int row = rr + 4 * j;
            float4 v = reinterpret_cast<const float4*>(SF)[(size_t)(s0 + row) * 128 + q];
            __nv_bfloat162 b0 = __floats2bfloat162_rn(v.x, v.y);
            __nv_bfloat162 b1 = __floats2bfloat162_rn(v.z, v.w);
            uint2 u;
            u.x = *reinterpret_cast<uint32_t*>(&b0);
            u.y = *reinterpret_cast<uint32_t*>(&b1);
            *reinterpret_cast<uint2*>(sm + FS_A_OFF + row * APITCH + q * 8) = u;
        }
    }
    // Stage B: Hn [64 rows][512 f] bf16 -> pitch 1040 (L2-hot).
    #pragma unroll 8
    for (int i = t; i < 64 * 64; i += 512) {
        int row = i >> 6;
        int c16 = i & 63;
        uint4 u = reinterpret_cast<const uint4*>(g_HnB)[row * 64 + c16];
        *reinterpret_cast<uint4*>(sm + FS_B_OFF + row * APITCH + c16 * 16) = u;
    }
    __syncthreads();

    // Per-row sumsq from staged bf16 (warp w -> rows 2w, 2w+1).
    #pragma unroll
    for (int rr = 0; rr < 2; rr++) {
        int row = wid * 2 + rr;
        const uint32_t* rp = reinterpret_cast<const uint32_t*>(sm + FS_A_OFF + row * APITCH);
        float sq = 0.f;
        #pragma unroll
        for (int j = 0; j < 8; j++) {
            uint32_t pk = rp[lid + 32 * j];
            __nv_bfloat162 bb = *reinterpret_cast<__nv_bfloat162*>(&pk);
            float2 f = __bfloat1622float2(bb);
            sq += f.x * f.x + f.y * f.y;
        }
        #pragma unroll
        for (int o = 16; o > 0; o >>= 1) sq += __shfl_down_sync(0xffffffffu, sq, o);
        if (lid == 0) s_sinv[row] = 0.5f / (sqrtf(sq) + EPSV);
    }
    __syncthreads();

    // Warp tile: m0 = 16*(wid>>3), n0 = 8*(wid&7). One m16n8k16 per k-step.
    int m0 = (wid >> 3) * 16;
    int n0 = (wid & 7) * 8;
    float c[4] = {0.f, 0.f, 0.f, 0.f};

    uint32_t aBase = smA + (uint32_t)(m0 + (lid & 15)) * APITCH + ((lid >> 4) << 4);
    uint32_t bBase = smB + (uint32_t)(n0 + (lid & 7)) * APITCH + (((lid >> 3) & 1) << 4);

    #pragma unroll 8
    for (int k = 0; k < FF; k += 16) {
        uint32_t a[4], b0v, b1v;
        LDSM_X4(a, aBase + k * 2);
        LDSM_X2(b0v, b1v, bBase + k * 2);
        mma_bf16(c, a, b0v, b1v);
    }

    // Epilogue: rows r0=m0+lid/4, r1=r0+8; col = n0 + 2*(lid&3).
    int r0 = m0 + (lid >> 2);
    int r1 = r0 + 8;
    int col = n0 + 2 * (lid & 3);
    float sc0 = s_sinv[r0];
    float sc1 = s_sinv[r1];
    __half2 h0 = __floats2half2_rn(c[0] * sc0 + 0.5f, c[1] * sc0 + 0.5f);
    __half2 h1 = __floats2half2_rn(c[2] * sc1 + 0.5f, c[3] * sc1 + 0.5f);
    *reinterpret_cast<__half2*>(&g_simT[(size_t)(s0 + r0) * 64 + col]) = h0;
    *reinterpret_cast<__half2*>(&g_simT[(size_t)(s0 + r1) * 64 + col]) = h1;
}

// ---------------- K4: per-disease gather-reduce -> out -----------------------
__global__ void __launch_bounds__(256) out_kernel(float* __restrict__ out, int D) {
    int d  = blockIdx.x;
    int t  = threadIdx.x;             // 256
    int l  = t & 31;
    int eg = t >> 5;                  // 0..7
    int i0 = g_start[d];
    int i1 = g_start[d + 1];
    float ax = 0.f, ay = 0.f;
    #pragma unroll 2
    for (int i = i0 + eg; i < i1; i += 8) {
        int2 p = g_epack[i];
        float w = __int_as_float(p.y);
        __half2 sv = *reinterpret_cast<const __half2*>(&g_simT[p.x * 64 + 2 * l]);
        float2 f = __half22float2(sv);
        ax += w * f.x;
        ay += w * f.y;
    }
    __shared__ float sx[256], sy[256];
    sx[t] = ax; sy[t] = ay;
    __syncthreads();
    if (eg == 0) {
        float tx = 0.f, ty = 0.f;
        #pragma unroll
        for (int k = 0; k < 8; k++) { tx += sx[32 * k + l]; ty += sy[32 * k + l]; }
        int b0 = 2 * l;
        out[(size_t)b0 * D + d]       = ETA * g_gnorm[b0]     * tx;
        out[(size_t)(b0 + 1) * D + d] = ETA * g_gnorm[b0 + 1] * ty;
    }
}

// ---------------- launch: single stream, 4 kernels ---------------------------
extern "C" void kernel_launch(void* const* d_in, const int* in_sizes, int n_in,
                              void* d_out, int out_size) {
    const float* H  = (const float*)d_in[0];   // [B,F]
    const float* G  = (const float*)d_in[1];   // [B,F]
    const float* SF = (const float*)d_in[2];   // [S,F]
    const float* ew = (const float*)d_in[3];   // [E]
    const int*   ed = (const int*)d_in[4];     // [E]
    const int*   es = (const int*)d_in[5];     // [E]
    float* out = (float*)d_out;

    int E  = in_sizes[3];                      // 500000
    int D  = 1024;
    int CH = (E + NBLK - 1) / NBLK;            // edges per partition block

    static int smem_set = 0;
    if (!smem_set) {
        cudaFuncSetAttribute(fused_kernel,
                             cudaFuncAttributeMaxDynamicSharedMemorySize,
                             FS_SMEM);
        smem_set = 1;
    }

    combo1_kernel<<<NBLK + 8, 1024>>>(H, G, ed, E, CH);
    scan_pre_kernel<<<8, 1024>>>();
    fused_kernel<<<NBLK + NSIM, 512, FS_SMEM>>>(SF, ew, ed, es, E, CH);
    out_kernel<<<D, 256>>>(out, D);
}

// round 12
// speedup vs baseline: 3.9554x; 1.1477x over previous
#include <cuda_runtime.h>
#include <cuda_fp16.h>
#include <cuda_bf16.h>
#include <math.h>
#include <stdint.h>

// Shapes fixed by the dataset: B=64, F=512, S=8192, E=500000, D=1024.
#define BB    64
#define FF    512
#define S_MAX 8192
#define E_MAX 500000
#define D_MAX 1024
#define NBLK  296            // edge partition blocks (hist & scat must match)
#define NSIM  256            // sim tiles: 8192 / 32
#define EPSV  1e-8f
#define ETA   0.01f

// ---------------- device scratch (static: no allocations allowed) ------------
__device__ __nv_bfloat16 g_HnB[BB * FF];   // normalized heatmap, bf16 [b][f]
__device__ float  g_gnorm[BB];             // ||grad_b||
__device__ __half g_simT[S_MAX * BB];      // sim transposed [s][b], fp16
__device__ int    g_blkcnt[NBLK * D_MAX];  // per-block histograms -> local prefixes
__device__ int    g_cnt[D_MAX];            // per-disease totals
__device__ int    g_start[D_MAX + 1];      // bucket starts
__device__ int2   g_epack[E_MAX];          // (sign, weight-bits) bucketed by disease
__device__ int    g_tick = 0;              // decoupled-scan ticket (reset each run)

// ================= portable tensor-core helpers (sm_80+) =====================
__device__ __forceinline__ uint32_t smem_u32(const void* p) {
    uint32_t a;
    asm("{ .reg .u64 t; cvta.to.shared.u64 t, %1; cvt.u32.u64 %0, t; }"
        : "=r"(a) : "l"(p));
    return a;
}
#define LDSM_X4(r, addr)                                                       \
    asm volatile("ldmatrix.sync.aligned.m8n8.x4.shared.b16 {%0,%1,%2,%3}, [%4];" \
        : "=r"((r)[0]), "=r"((r)[1]), "=r"((r)[2]), "=r"((r)[3])               \
        : "r"(addr))
#define LDSM_X2(r0, r1, addr)                                                  \
    asm volatile("ldmatrix.sync.aligned.m8n8.x2.shared.b16 {%0,%1}, [%2];"     \
        : "=r"(r0), "=r"(r1) : "r"(addr))
__device__ __forceinline__ void mma_bf16(float* c, const uint32_t* a,
                                         uint32_t b0, uint32_t b1) {
    asm volatile(
        "mma.sync.aligned.m16n8k16.row.col.f32.bf16.bf16.f32 "
        "{%0,%1,%2,%3}, {%4,%5,%6,%7}, {%8,%9}, {%0,%1,%2,%3};"
        : "+f"(c[0]), "+f"(c[1]), "+f"(c[2]), "+f"(c[3])
        : "r"(a[0]), "r"(a[1]), "r"(a[2]), "r"(a[3]), "r"(b0), "r"(b1));
}

// ---------------- K1: fused prep_h (blocks 0..7) + histogram (blocks 8+) -----
__global__ void __launch_bounds__(1024, 1)
combo1_kernel(const float* __restrict__ H,
              const float* __restrict__ G,
              const int* __restrict__ ed, int E, int CH) {
    __shared__ int h[D_MAX];               // hist branch
    __shared__ float wsh[8][4], wsg[8][4]; // prep branch
    __shared__ float sinvs[8];
    int t = threadIdx.x;                   // 1024

    if (blockIdx.x < 8) {
        int r  = t >> 7;                   // row group 0..7
        int tt = t & 127;
        int b  = blockIdx.x * 8 + r;       // 0..63
        float4 hv = reinterpret_cast<const float4*>(H + b * FF)[tt];
        float4 gv = reinterpret_cast<const float4*>(G + b * FF)[tt];
        float sh = hv.x * hv.x + hv.y * hv.y + hv.z * hv.z + hv.w * hv.w;
        float sg = gv.x * gv.x + gv.y * gv.y + gv.z * gv.z + gv.w * gv.w;
        #pragma unroll
        for (int o = 16; o > 0; o >>= 1) {
            sh += __shfl_down_sync(0xffffffffu, sh, o);
            sg += __shfl_down_sync(0xffffffffu, sg, o);
        }
        if ((tt & 31) == 0) { wsh[r][tt >> 5] = sh; wsg[r][tt >> 5] = sg; }
        __syncthreads();
        if (tt == 0) {
            float th = wsh[r][0] + wsh[r][1] + wsh[r][2] + wsh[r][3];
            float tg = wsg[r][0] + wsg[r][1] + wsg[r][2] + wsg[r][3];
            sinvs[r] = 1.0f / (sqrtf(th) + EPSV);
            g_gnorm[b] = sqrtf(tg);
        }
        __syncthreads();
        float inv = sinvs[r];
        __nv_bfloat162 p0 = __floats2bfloat162_rn(hv.x * inv, hv.y * inv);
        __nv_bfloat162 p1 = __floats2bfloat162_rn(hv.z * inv, hv.w * inv);
        uint2 u;
        u.x = *reinterpret_cast<uint32_t*>(&p0);
        u.y = *reinterpret_cast<uint32_t*>(&p1);
        reinterpret_cast<uint2*>(g_HnB)[b * 128 + tt] = u;
    } else {
        int hb = blockIdx.x - 8;           // 0..NBLK-1
        h[t] = 0;
        __syncthreads();
        int e0 = hb * CH;
        int e1 = min(E, e0 + CH);
        for (int e = e0 + t; e < e1; e += 1024) atomicAdd(&h[ed[e]], 1);
        __syncthreads();
        g_blkcnt[hb * D_MAX + t] = h[t];
    }
}

// ---------------- K2: per-block prefixes + fused final scan ------------------
__global__ void __launch_bounds__(1024, 1) scan_pre_kernel() {
    int g  = blockIdx.x;           // 8 blocks, 128 diseases each
    int t  = threadIdx.x;          // 1024
    int dl = t & 127;
    int c  = t >> 7;               // 8 chunks over NBLK
    int d  = g * 128 + dl;
    const int per = (NBLK + 7) / 8;
    int b0 = c * per, b1 = min(NBLK, b0 + per);
    int sum = 0;
    for (int blk = b0; blk < b1; blk++) sum += g_blkcnt[blk * D_MAX + d];
    __shared__ int ch[8][128];
    ch[c][dl] = sum;
    __syncthreads();
    if (c == 0) {
        int r = 0;
        #pragma unroll
        for (int j = 0; j < 8; j++) { int v = ch[j][dl]; ch[j][dl] = r; r += v; }
        g_cnt[d] = r;
    }
    __syncthreads();
    int run = ch[c][dl];
    for (int blk = b0; blk < b1; blk++) {
        int idx = blk * D_MAX + d;
        int v = g_blkcnt[idx];
        g_blkcnt[idx] = run;       // within-disease exclusive prefix over blocks
        run += v;
    }

    // ---- decoupled final scan: last-arriving block scans g_cnt -> g_start ---
    __shared__ int is_last;
    __threadfence();
    if (t == 0) is_last = (atomicAdd(&g_tick, 1) == gridDim.x - 1) ? 1 : 0;
    __syncthreads();
    if (!is_last) return;

    __shared__ int wtot[32];
    int v = g_cnt[t];
    int l = t & 31, w = t >> 5;
    int inc = v;
    #pragma unroll
    for (int o = 1; o < 32; o <<= 1) {
        int n = __shfl_up_sync(0xffffffffu, inc, o);
        if (l >= o) inc += n;
    }
    if (l == 31) wtot[w] = inc;
    __syncthreads();
    if (w == 0) {
        int x = wtot[l];
        #pragma unroll
        for (int o = 1; o < 32; o <<= 1) {
            int n = __shfl_up_sync(0xffffffffu, x, o);
            if (l >= o) x += n;
        }
        wtot[l] = x;               // inclusive warp totals
    }
    __syncthreads();
    int base = (w > 0) ? wtot[w - 1] : 0;
    g_start[t + 1] = base + inc;
    if (t == 0) { g_start[0] = 0; g_tick = 0; }   // reset ticket for replay
}

// ---------------- K3: FUSED scatter + sim (independent chains, one launch) ---
// 512 threads, 2 blocks/SM (regs<=64, smem ~98KB). Interleaved block mapping:
// odd blocks (first 512) are sim tiles, so wave 1 runs ~148 of each kind.
// sim tile: M=32 signs x N=64 batch x K=512; warp tile 16x8 (16 warps).
#define APITCH    1040                      // bytes per 512-bf16 row (+16 pad)
#define FS_A_OFF  0
#define FS_B_OFF  (32 * APITCH)
#define FS_SMEM   (96 * APITCH)             // 99840 B

__global__ void __launch_bounds__(512, 2)
fused_kernel(const float* __restrict__ SF,
             const float* __restrict__ ew,
             const int* __restrict__ ed,
             const int* __restrict__ es, int E, int CH) {
    extern __shared__ char sm[];
    int t   = threadIdx.x;         // 512
    int bid = blockIdx.x;

    bool is_sim = (bid & 1) && ((bid >> 1) < NSIM);
    if (!is_sim) {
        // ================== scat branch ==================
        int scid = bid - min((bid + 1) >> 1, NSIM);   // 0..NBLK-1
        int* cur = reinterpret_cast<int*>(sm);
        cur[t]       = g_blkcnt[scid * D_MAX + t]       + g_start[t];
        cur[t + 512] = g_blkcnt[scid * D_MAX + t + 512] + g_start[t + 512];
        __syncthreads();
        int e0 = scid * CH;
        int e1 = min(E, e0 + CH);
        for (int e = e0 + t; e < e1; e += 512) {
            int d = ed[e];
            int pos = atomicAdd(&cur[d], 1);
            g_epack[pos] = make_int2(es[e], __float_as_int(ew[e]));
        }
        return;
    }

    // ================== sim branch ==================
    int sid = bid >> 1;            // 0..NSIM-1
    int s0  = sid * 32;
    int wid = t >> 5;              // 0..15
    int lid = t & 31;
    __shared__ float s_sinv[32];
    uint32_t smA = smem_u32(sm) + FS_A_OFF;
    uint32_t smB = smem_u32(sm) + FS_B_OFF;

    // Stage A: S tile [32 rows][512 f] fp32 -> bf16, pitch 1040 (MLP 8).
    {
        int q  = t & 127;
        int rr = t >> 7;           // 0..3
        #pragma unroll 8
        for (int j = 0; j < 8; j++) {
            int row = rr + 4 * j;
            float4 v = reinterpret_cast<const float4*>(SF)[(size_t)(s0 + row) * 128 + q];
            __nv_bfloat162 b0 = __floats2bfloat162_rn(v.x, v.y);
            __nv_bfloat162 b1 = __floats2bfloat162_rn(v.z, v.w);
            uint2 u;
            u.x = *reinterpret_cast<uint32_t*>(&b0);
            u.y = *reinterpret_cast<uint32_t*>(&b1);
            *reinterpret_cast<uint2*>(sm + FS_A_OFF + row * APITCH + q * 8) = u;
        }
    }
    // Stage B: Hn [64 rows][512 f] bf16 -> pitch 1040 (L2-hot).
    #pragma unroll 8
    for (int i = t; i < 64 * 64; i += 512) {
        int row = i >> 6;
        int c16 = i & 63;
        uint4 u = reinterpret_cast<const uint4*>(g_HnB)[row * 64 + c16];
        *reinterpret_cast<uint4*>(sm + FS_B_OFF + row * APITCH + c16 * 16) = u;
    }
    __syncthreads();

    // Per-row sumsq from staged bf16 (warp w -> rows 2w, 2w+1).
    #pragma unroll
    for (int rr = 0; rr < 2; rr++) {
        int row = wid * 2 + rr;
        const uint32_t* rp = reinterpret_cast<const uint32_t*>(sm + FS_A_OFF + row * APITCH);
        float sq = 0.f;
        #pragma unroll
        for (int j = 0; j < 8; j++) {
            uint32_t pk = rp[lid + 32 * j];
            __nv_bfloat162 bb = *reinterpret_cast<__nv_bfloat162*>(&pk);
            float2 f = __bfloat1622float2(bb);
            sq += f.x * f.x + f.y * f.y;
        }
        #pragma unroll
        for (int o = 16; o > 0; o >>= 1) sq += __shfl_down_sync(0xffffffffu, sq, o);
        if (lid == 0) s_sinv[row] = 0.5f / (sqrtf(sq) + EPSV);
    }
    __syncthreads();

    // Warp tile: m0 = 16*(wid>>3), n0 = 8*(wid&7). One m16n8k16 per k-step.
    int m0 = (wid >> 3) * 16;
    int n0 = (wid & 7) * 8;
    float c[4] = {0.f, 0.f, 0.f, 0.f};

    uint32_t aBase = smA + (uint32_t)(m0 + (lid & 15)) * APITCH + ((lid >> 4) << 4);
    uint32_t bBase = smB + (uint32_t)(n0 + (lid & 7)) * APITCH + (((lid >> 3) & 1) << 4);

    #pragma unroll 8
    for (int k = 0; k < FF; k += 16) {
        uint32_t a[4], b0v, b1v;
        LDSM_X4(a, aBase + k * 2);
        LDSM_X2(b0v, b1v, bBase + k * 2);
        mma_bf16(c, a, b0v, b1v);
    }

    // Epilogue: rows r0=m0+lid/4, r1=r0+8; col = n0 + 2*(lid&3).
    int r0 = m0 + (lid >> 2);
    int r1 = r0 + 8;
    int col = n0 + 2 * (lid & 3);
    float sc0 = s_sinv[r0];
    float sc1 = s_sinv[r1];
    __half2 h0 = __floats2half2_rn(c[0] * sc0 + 0.5f, c[1] * sc0 + 0.5f);
    __half2 h1 = __floats2half2_rn(c[2] * sc1 + 0.5f, c[3] * sc1 + 0.5f);
    *reinterpret_cast<__half2*>(&g_simT[(size_t)(s0 + r0) * 64 + col]) = h0;
    *reinterpret_cast<__half2*>(&g_simT[(size_t)(s0 + r1) * 64 + col]) = h1;
}

// ---------------- K4: per-disease gather-reduce -> out -----------------------
// 512 threads = 16 edge-groups x 32 lanes. Software-pipelined: batches of 4
// independent epack loads, then 4 simT loads (MLP=4 on the dependent chain).
__global__ void __launch_bounds__(512) out_kernel(float* __restrict__ out, int D) {
    int d  = blockIdx.x;
    int t  = threadIdx.x;             // 512
    int l  = t & 31;
    int eg = t >> 5;                  // 0..15
    int i0 = g_start[d];
    int i1 = g_start[d + 1];
    const int STR = 16;
    float ax = 0.f, ay = 0.f;

    int i = i0 + eg;
    for (; i + 3 * STR < i1; i += 4 * STR) {
        int2 p0 = g_epack[i];
        int2 p1 = g_epack[i + STR];
        int2 p2 = g_epack[i + 2 * STR];
        int2 p3 = g_epack[i + 3 * STR];
        __half2 v0 = *reinterpret_cast<const __half2*>(&g_simT[p0.x * 64 + 2 * l]);
        __half2 v1 = *reinterpret_cast<const __half2*>(&g_simT[p1.x * 64 + 2 * l]);
        __half2 v2 = *reinterpret_cast<const __half2*>(&g_simT[p2.x * 64 + 2 * l]);
        __half2 v3 = *reinterpret_cast<const __half2*>(&g_simT[p3.x * 64 + 2 * l]);
        float2 f0 = __half22float2(v0);
        float2 f1 = __half22float2(v1);
        float2 f2 = __half22float2(v2);
        float2 f3 = __half22float2(v3);
        float w0 = __int_as_float(p0.y);
        float w1 = __int_as_float(p1.y);
        float w2 = __int_as_float(p2.y);
        float w3 = __int_as_float(p3.y);
        ax += w0 * f0.x + w1 * f1.x + w2 * f2.x + w3 * f3.x;
        ay += w0 * f0.y + w1 * f1.y + w2 * f2.y + w3 * f3.y;
    }
    for (; i < i1; i += STR) {
        int2 p = g_epack[i];
        float w = __int_as_float(p.y);
        __half2 sv = *reinterpret_cast<const __half2*>(&g_simT[p.x * 64 + 2 * l]);
        float2 f = __half22float2(sv);
        ax += w * f.x;
        ay += w * f.y;
    }

    __shared__ float sx[512], sy[512];
    sx[t] = ax; sy[t] = ay;
    __syncthreads();
    if (eg == 0) {
        float tx = 0.f, ty = 0.f;
        #pragma unroll
        for (int k = 0; k < 16; k++) { tx += sx[32 * k + l]; ty += sy[32 * k + l]; }
        int b0 = 2 * l;
        out[(size_t)b0 * D + d]       = ETA * g_gnorm[b0]     * tx;
        out[(size_t)(b0 + 1) * D + d] = ETA * g_gnorm[b0 + 1] * ty;
    }
}

// ---------------- launch: single stream, 4 kernels ---------------------------
extern "C" void kernel_launch(void* const* d_in, const int* in_sizes, int n_in,
                              void* d_out, int out_size) {
    const float* H  = (const float*)d_in[0];   // [B,F]
    const float* G  = (const float*)d_in[1];   // [B,F]
    const float* SF = (const float*)d_in[2];   // [S,F]
    const float* ew = (const float*)d_in[3];   // [E]
    const int*   ed = (const int*)d_in[4];     // [E]
    const int*   es = (const int*)d_in[5];     // [E]
    float* out = (float*)d_out;

    int E  = in_sizes[3];                      // 500000
    int D  = 1024;
    int CH = (E + NBLK - 1) / NBLK;            // edges per partition block

    static int smem_set = 0;
    if (!smem_set) {
        cudaFuncSetAttribute(fused_kernel,
                             cudaFuncAttributeMaxDynamicSharedMemorySize,
                             FS_SMEM);
        smem_set = 1;
    }

    combo1_kernel<<<NBLK + 8, 1024>>>(H, G, ed, E, CH);
    scan_pre_kernel<<<8, 1024>>>();
    fused_kernel<<<NBLK + NSIM, 512, FS_SMEM>>>(SF, ew, ed, es, E, CH);
    out_kernel<<<D, 512>>>(out, D);
}

// round 16
// speedup vs baseline: 3.9586x; 1.0008x over previous
#include <cuda_runtime.h>
#include <cuda_fp16.h>
#include <cuda_bf16.h>
#include <math.h>
#include <stdint.h>

// Shapes fixed by the dataset: B=64, F=512, S=8192, E=500000, D=1024.
#define BB    64
#define FF    512
#define S_MAX 8192
#define E_MAX 500000
#define D_MAX 1024
#define NBLK  296            // edge partition blocks (hist & scat must match)
#define NSIM  256            // sim tiles: 8192 / 32
#define EPSV  1e-8f
#define ETA   0.01f

// ---------------- device scratch (static: no allocations allowed) ------------
__device__ __nv_bfloat16 g_HnB[BB * FF];   // normalized heatmap, bf16 [b][f]
__device__ float  g_gnorm[BB];             // ||grad_b||
__device__ __half g_simT[S_MAX * BB];      // sim transposed [s][b], fp16
__device__ int    g_blkcnt[NBLK * D_MAX];  // per-block histograms -> local prefixes
__device__ int    g_cnt[D_MAX];            // per-disease totals
__device__ int    g_start[D_MAX + 1];      // bucket starts
__device__ int2   g_epack[E_MAX];          // (sign, weight-bits) bucketed by disease
__device__ int    g_tick = 0;              // decoupled-scan ticket (reset each run)

// ================= portable tensor-core helpers (sm_80+) =====================
__device__ __forceinline__ uint32_t smem_u32(const void* p) {
    uint32_t a;
    asm("{ .reg .u64 t; cvta.to.shared.u64 t, %1; cvt.u32.u64 %0, t; }"
        : "=r"(a) : "l"(p));
    return a;
}
#define LDSM_X4(r, addr)                                                       \
    asm volatile("ldmatrix.sync.aligned.m8n8.x4.shared.b16 {%0,%1,%2,%3}, [%4];" \
        : "=r"((r)[0]), "=r"((r)[1]), "=r"((r)[2]), "=r"((r)[3])               \
        : "r"(addr))
#define LDSM_X2(r0, r1, addr)                                                  \
    asm volatile("ldmatrix.sync.aligned.m8n8.x2.shared.b16 {%0,%1}, [%2];"     \
        : "=r"(r0), "=r"(r1) : "r"(addr))
__device__ __forceinline__ void mma_bf16(float* c, const uint32_t* a,
                                         uint32_t b0, uint32_t b1) {
    asm volatile(
        "mma.sync.aligned.m16n8k16.row.col.f32.bf16.bf16.f32 "
        "{%0,%1,%2,%3}, {%4,%5,%6,%7}, {%8,%9}, {%0,%1,%2,%3};"
        : "+f"(c[0]), "+f"(c[1]), "+f"(c[2]), "+f"(c[3])
        : "r"(a[0]), "r"(a[1]), "r"(a[2]), "r"(a[3]), "r"(b0), "r"(b1));
}

// ---------------- K1: fused prep_h (blocks 0..7) + histogram (blocks 8+) -----
__global__ void __launch_bounds__(1024, 1)
combo1_kernel(const float* __restrict__ H,
              const float* __restrict__ G,
              const int* __restrict__ ed, int E, int CH) {
    __shared__ int h[D_MAX];               // hist branch
    __shared__ float wsh[8][4], wsg[8][4]; // prep branch
    __shared__ float sinvs[8];
    int t = threadIdx.x;                   // 1024

    if (blockIdx.x < 8) {
        int r  = t >> 7;                   // row group 0..7
        int tt = t & 127;
        int b  = blockIdx.x * 8 + r;       // 0..63
        float4 hv = reinterpret_cast<const float4*>(H + b * FF)[tt];
        float4 gv = reinterpret_cast<const float4*>(G + b * FF)[tt];
        float sh = hv.x * hv.x + hv.y * hv.y + hv.z * hv.z + hv.w * hv.w;
        float sg = gv.x * gv.x + gv.y * gv.y + gv.z * gv.z + gv.w * gv.w;
        #pragma unroll
        for (int o = 16; o > 0; o >>= 1) {
            sh += __shfl_down_sync(0xffffffffu, sh, o);
            sg += __shfl_down_sync(0xffffffffu, sg, o);
        }
        if ((tt & 31) == 0) { wsh[r][tt >> 5] = sh; wsg[r][tt >> 5] = sg; }
        __syncthreads();
        if (tt == 0) {
            float th = wsh[r][0] + wsh[r][1] + wsh[r][2] + wsh[r][3];
            float tg = wsg[r][0] + wsg[r][1] + wsg[r][2] + wsg[r][3];
            sinvs[r] = 1.0f / (sqrtf(th) + EPSV);
            g_gnorm[b] = sqrtf(tg);
        }
        __syncthreads();
        float inv = sinvs[r];
        __nv_bfloat162 p0 = __floats2bfloat162_rn(hv.x * inv, hv.y * inv);
        __nv_bfloat162 p1 = __floats2bfloat162_rn(hv.z * inv, hv.w * inv);
        uint2 u;
        u.x = *reinterpret_cast<uint32_t*>(&p0);
        u.y = *reinterpret_cast<uint32_t*>(&p1);
        reinterpret_cast<uint2*>(g_HnB)[b * 128 + tt] = u;
    } else {
        int hb = blockIdx.x - 8;           // 0..NBLK-1
        h[t] = 0;
        __syncthreads();
        int e0 = hb * CH;
        int e1 = min(E, e0 + CH);
        for (int e = e0 + t; e < e1; e += 1024) atomicAdd(&h[ed[e]], 1);
        __syncthreads();
        g_blkcnt[hb * D_MAX + t] = h[t];
    }
}

// ---------------- K2: per-block prefixes + fused final scan ------------------
__global__ void __launch_bounds__(1024, 1) scan_pre_kernel() {
    int g  = blockIdx.x;           // 8 blocks, 128 diseases each
    int t  = threadIdx.x;          // 1024
    int dl = t & 127;
    int c  = t >> 7;               // 8 chunks over NBLK
    int d  = g * 128 + dl;
    const int per = (NBLK + 7) / 8;
    int b0 = c * per, b1 = min(NBLK, b0 + per);
    int sum = 0;
    for (int blk = b0; blk < b1; blk++) sum += g_blkcnt[blk * D_MAX + d];
    __shared__ int ch[8][128];
    ch[c][dl] = sum;
    __syncthreads();
    if (c == 0) {
        int r = 0;
        #pragma unroll
        for (int j = 0; j < 8; j++) { int v = ch[j][dl]; ch[j][dl] = r; r += v; }
        g_cnt[d] = r;
    }
    __syncthreads();
    int run = ch[c][dl];
    for (int blk = b0; blk < b1; blk++) {
        int idx = blk * D_MAX + d;
        int v = g_blkcnt[idx];
        g_blkcnt[idx] = run;       // within-disease exclusive prefix over blocks
        run += v;
    }

    // ---- decoupled final scan: last-arriving block scans g_cnt -> g_start ---
    __shared__ int is_last;
    __threadfence();
    if (t == 0) is_last = (atomicAdd(&g_tick, 1) == gridDim.x - 1) ? 1 : 0;
    __syncthreads();
    if (!is_last) return;

    __shared__ int wtot[32];
    int v = g_cnt[t];
    int l = t & 31, w = t >> 5;
    int inc = v;
    #pragma unroll
    for (int o = 1; o < 32; o <<= 1) {
        int n = __shfl_up_sync(0xffffffffu, inc, o);
        if (l >= o) inc += n;
    }
    if (l == 31) wtot[w] = inc;
    __syncthreads();
    if (w == 0) {
        int x = wtot[l];
        #pragma unroll
        for (int o = 1; o < 32; o <<= 1) {
            int n = __shfl_up_sync(0xffffffffu, x, o);
            if (l >= o) x += n;
        }
        wtot[l] = x;               // inclusive warp totals
    }
    __syncthreads();
    int base = (w > 0) ? wtot[w - 1] : 0;
    g_start[t + 1] = base + inc;
    if (t == 0) { g_start[0] = 0; g_tick = 0; }   // reset ticket for replay
}

// ---------------- K3: FUSED scatter + sim (independent chains, one launch) ---
// 512 threads, 2 blocks/SM (regs<=64, smem ~98KB). Interleaved block mapping:
// odd blocks (first 512) are sim tiles, so wave 1 runs ~148 of each kind.
// sim tile: M=32 signs x N=64 batch x K=512; warp tile 16x8 (16 warps).
#define APITCH    1040                      // bytes per 512-bf16 row (+16 pad)
#define FS_A_OFF  0
#define FS_B_OFF  (32 * APITCH)
#define FS_SMEM   (96 * APITCH)             // 99840 B

__global__ void __launch_bounds__(512, 2)
fused_kernel(const float* __restrict__ SF,
             const float* __restrict__ ew,
             const int* __restrict__ ed,
             const int* __restrict__ es, int E, int CH) {
    extern __shared__ char sm[];
    int t   = threadIdx.x;         // 512
    int bid = blockIdx.x;

    bool is_sim = (bid & 1) && ((bid >> 1) < NSIM);
    if (!is_sim) {
        // ================== scat branch ==================
        int scid = bid - min((bid + 1) >> 1, NSIM);   // 0..NBLK-1
        int* cur = reinterpret_cast<int*>(sm);
        cur[t]       = g_blkcnt[scid * D_MAX + t]       + g_start[t];
        cur[t + 512] = g_blkcnt[scid * D_MAX + t + 512] + g_start[t + 512];
        __syncthreads();
        int e0 = scid * CH;
        int e1 = min(E, e0 + CH);
        for (int e = e0 + t; e < e1; e += 512) {
            int d = ed[e];
            int pos = atomicAdd(&cur[d], 1);
            g_epack[pos] = make_int2(es[e], __float_as_int(ew[e]));
        }
        return;
    }

    // ================== sim branch ==================
    int sid = bid >> 1;            // 0..NSIM-1
    int s0  = sid * 32;
    int wid = t >> 5;              // 0..15
    int lid = t & 31;
    __shared__ float s_sinv[32];
    uint32_t smA = smem_u32(sm) + FS_A_OFF;
    uint32_t smB = smem_u32(sm) + FS_B_OFF;

    // Stage A: S tile [32 rows][512 f] fp32 -> bf16, pitch 1040 (MLP 8).
    {
        int q  = t & 127;
        int rr = t >> 7;           // 0..3
        #pragma unroll 8
        for (int j = 0; j < 8; j++) {
            int row = rr + 4 * j;
            float4 v = reinterpret_cast<const float4*>(SF)[(size_t)(s0 + row) * 128 + q];
            __nv_bfloat162 b0 = __floats2bfloat162_rn(v.x, v.y);
            __nv_bfloat162 b1 = __floats2bfloat162_rn(v.z, v.w);
            uint2 u;
            u.x = *reinterpret_cast<uint32_t*>(&b0);
            u.y = *reinterpret_cast<uint32_t*>(&b1);
            *reinterpret_cast<uint2*>(sm + FS_A_OFF + row * APITCH + q * 8) = u;
        }
    }
    // Stage B: Hn [64 rows][512 f] bf16 -> pitch 1040 (L2-hot).
    #pragma unroll 8
    for (int i = t; i < 64 * 64; i += 512) {
        int row = i >> 6;
        int c16 = i & 63;
        uint4 u = reinterpret_cast<const uint4*>(g_HnB)[row * 64 + c16];
        *reinterpret_cast<uint4*>(sm + FS_B_OFF + row * APITCH + c16 * 16) = u;
    }
    __syncthreads();

    // Per-row sumsq from staged bf16 (warp w -> rows 2w, 2w+1).
    #pragma unroll
    for (int rr = 0; rr < 2; rr++) {
        int row = wid * 2 + rr;
        const uint32_t* rp = reinterpret_cast<const uint32_t*>(sm + FS_A_OFF + row * APITCH);
        float sq = 0.f;
        #pragma unroll
        for (int j = 0; j < 8; j++) {
            uint32_t pk = rp[lid + 32 * j];
            __nv_bfloat162 bb = *reinterpret_cast<__nv_bfloat162*>(&pk);
            float2 f = __bfloat1622float2(bb);
            sq += f.x * f.x + f.y * f.y;
        }
        #pragma unroll
        for (int o = 16; o > 0; o >>= 1) sq += __shfl_down_sync(0xffffffffu, sq, o);
        if (lid == 0) s_sinv[row] = 0.5f / (sqrtf(sq) + EPSV);
    }
    __syncthreads();

    // Warp tile: m0 = 16*(wid>>3), n0 = 8*(wid&7). One m16n8k16 per k-step.
    int m0 = (wid >> 3) * 16;
    int n0 = (wid & 7) * 8;
    float c[4] = {0.f, 0.f, 0.f, 0.f};

    uint32_t aBase = smA + (uint32_t)(m0 + (lid & 15)) * APITCH + ((lid >> 4) << 4);
    uint32_t bBase = smB + (uint32_t)(n0 + (lid & 7)) * APITCH + (((lid >> 3) & 1) << 4);

    #pragma unroll 8
    for (int k = 0; k < FF; k += 16) {
        uint32_t a[4], b0v, b1v;
        LDSM_X4(a, aBase + k * 2);
        LDSM_X2(b0v, b1v, bBase + k * 2);
        mma_bf16(c, a, b0v, b1v);
    }

    // Epilogue: rows r0=m0+lid/4, r1=r0+8; col = n0 + 2*(lid&3).
    int r0 = m0 + (lid >> 2);
    int r1 = r0 + 8;
    int col = n0 + 2 * (lid & 3);
    float sc0 = s_sinv[r0];
    float sc1 = s_sinv[r1];
    __half2 h0 = __floats2half2_rn(c[0] * sc0 + 0.5f, c[1] * sc0 + 0.5f);
    __half2 h1 = __floats2half2_rn(c[2] * sc1 + 0.5f, c[3] * sc1 + 0.5f);
    *reinterpret_cast<__half2*>(&g_simT[(size_t)(s0 + r0) * 64 + col]) = h0;
    *reinterpret_cast<__half2*>(&g_simT[(size_t)(s0 + r1) * 64 + col]) = h1;
}

// ---------------- K4: per-disease gather-reduce -> out -----------------------
// 512 threads = 16 edge-groups x 32 lanes. Uniform depth-8 batches: every
// load burst issues 8 independent epack + 8 simT loads (MLP=8); slots past
// the bucket end are clamped to a valid address with weight forced to 0
// (per-warp-uniform condition, no divergence, no serial tail).
__global__ void __launch_bounds__(512) out_kernel(float* __restrict__ out, int D) {
    int d  = blockIdx.x;
    int t  = threadIdx.x;             // 512
    int l  = t & 31;
    int eg = t >> 5;                  // 0..15
    int i0 = g_start[d];
    int i1 = g_start[d + 1];
    const int STR = 16;
    float ax = 0.f, ay = 0.f;

    for (int i = i0 + eg; i < i1; i += 8 * STR) {
        int2  p[8];
        float w[8];
        __half2 v[8];
        #pragma unroll
        for (int k = 0; k < 8; k++) {
            int idx   = i + k * STR;
            bool ok   = idx < i1;
            int  idxc = ok ? idx : i0;
            p[k] = g_epack[idxc];
            w[k] = ok ? __int_as_float(p[k].y) : 0.0f;
        }
        #pragma unroll
        for (int k = 0; k < 8; k++)
            v[k] = *reinterpret_cast<const __half2*>(&g_simT[p[k].x * 64 + 2 * l]);
        #pragma unroll
        for (int k = 0; k < 8; k++) {
            float2 f = __half22float2(v[k]);
            ax += w[k] * f.x;
            ay += w[k] * f.y;
        }
    }

    __shared__ float sx[512], sy[512];
    sx[t] = ax; sy[t] = ay;
    __syncthreads();
    if (eg == 0) {
        float tx = 0.f, ty = 0.f;
        #pragma unroll
        for (int k = 0; k < 16; k++) { tx += sx[32 * k + l]; ty += sy[32 * k + l]; }
        int b0 = 2 * l;
        out[(size_t)b0 * D + d]       = ETA * g_gnorm[b0]     * tx;
        out[(size_t)(b0 + 1) * D + d] = ETA * g_gnorm[b0 + 1] * ty;
    }
}

// ---------------- launch: single stream, 4 kernels ---------------------------
extern "C" void kernel_launch(void* const* d_in, const int* in_sizes, int n_in,
                              void* d_out, int out_size) {
    const float* H  = (const float*)d_in[0];   // [B,F]
    const float* G  = (const float*)d_in[1];   // [B,F]
    const float* SF = (const float*)d_in[2];   // [S,F]
    const float* ew = (const float*)d_in[3];   // [E]
    const int*   ed = (const int*)d_in[4];     // [E]
    const int*   es = (const int*)d_in[5];     // [E]
    float* out = (float*)d_out;

    int E  = in_sizes[3];                      // 500000
    int D  = 1024;
    int CH = (E + NBLK - 1) / NBLK;            // edges per partition block

    static int smem_set = 0;
    if (!smem_set) {
        cudaFuncSetAttribute(fused_kernel,
                             cudaFuncAttributeMaxDynamicSharedMemorySize,
                             FS_SMEM);
        smem_set = 1;
    }

    combo1_kernel<<<NBLK + 8, 1024>>>(H, G, ed, E, CH);
    scan_pre_kernel<<<8, 1024>>>();
    fused_kernel<<<NBLK + NSIM, 512, FS_SMEM>>>(SF, ew, ed, es, E, CH);
    out_kernel<<<D, 512>>>(out, D);
}